// round 8
// baseline (speedup 1.0000x reference)
#include <cuda_runtime.h>
#include <math.h>
#include <stdint.h>

// Problem constants
#define BB   2
#define SS   2048
#define EE   1024
#define NHH  16
#define NKVV 4
#define HDD  64
#define GCH  12
#define MM   (BB * SS)        // 4096 tokens
#define QDIM (NHH * HDD)      // 1024
#define KVDIM (NKVV * HDD)    // 256

// Scratch (device globals: allocation-free rule)
__device__ float g_q[MM * QDIM];    // 16 MB
__device__ float g_k[MM * KVDIM];   //  4 MB
__device__ float g_v[MM * KVDIM];   //  4 MB
__device__ float g_y[MM * QDIM];    // 16 MB

// ---------------------------------------------------------------------------
// tf32 helpers
// ---------------------------------------------------------------------------
__device__ __forceinline__ unsigned f2tf(float x) {
    unsigned u;
    asm("cvt.rna.tf32.f32 %0, %1;" : "=r"(u) : "f"(x));
    return u;
}

// D += A(16x8) * B(8x8), tf32 inputs, f32 accumulate
__device__ __forceinline__ void mma8(float* c,
                                     unsigned a0, unsigned a1, unsigned a2, unsigned a3,
                                     unsigned b0, unsigned b1) {
    asm volatile(
        "mma.sync.aligned.m16n8k8.row.col.f32.tf32.tf32.f32 "
        "{%0,%1,%2,%3},{%4,%5,%6,%7},{%8,%9},{%0,%1,%2,%3};"
        : "+f"(c[0]), "+f"(c[1]), "+f"(c[2]), "+f"(c[3])
        : "r"(a0), "r"(a1), "r"(a2), "r"(a3), "r"(b0), "r"(b1));
}

__device__ __forceinline__ float* qkv_ptr(int row, int col) {
    if (col < QDIM)         return &g_q[(size_t)row * QDIM + col];
    if (col < QDIM + KVDIM) return &g_k[(size_t)row * KVDIM + (col - QDIM)];
    return &g_v[(size_t)row * KVDIM + (col - QDIM - KVDIM)];
}

// Pair-interleaved smem layout: within each 8-word group, logical col c sits
// at physical (c&~7) + 2*(c&3) + ((c>>2)&1), so (c, c+4) pairs are adjacent
// and fragment loads become one LDS.64. Pad strides chosen == 8 (mod 32) so
// the 64-bit loads are phase-conflict-free.

// ---------------------------------------------------------------------------
// GEMM 1: [q|k|v] = X (4096x1024) @ [Wq;Wk;Wv]^T (1536x1024), tf32 mma
// 128x128 block, k-chunk 32, 8 warps (2x4), warp tile 64x32, reg prefetch
// ---------------------------------------------------------------------------
#define GPAD 40

__global__ void __launch_bounds__(256) gemm_qkv(
    const float* __restrict__ X,
    const float* __restrict__ Wq,
    const float* __restrict__ Wk,
    const float* __restrict__ Wv)
{
    __shared__ unsigned As[128 * GPAD];
    __shared__ unsigned Bs[128 * GPAD];

    const int bm = blockIdx.y * 128;
    const int bn = blockIdx.x * 128;
    const int tid = threadIdx.x;
    const int lane = tid & 31;
    const int wid = tid >> 5;
    const int wm = (wid >> 2) * 64;   // 0 or 64
    const int wn = (wid & 3) * 32;    // 0..96
    const int gy = lane >> 2;         // 0..7
    const int gx = lane & 3;          // 0..3

    const int srow = tid >> 3;          // base row 0..31 (stride 32 via p)
    const int sc4  = (tid & 7) * 4;     // logical col 0,4,..,28
    const int soff = (sc4 & ~7) + ((sc4 >> 2) & 1);  // interleaved store base

    const float* aptr = X + (size_t)(bm + srow) * EE + sc4;
    const float* bptr[4];
    #pragma unroll
    for (int p = 0; p < 4; p++) {
        const int n = bn + srow + 32 * p;
        if (n < QDIM)                bptr[p] = Wq + (size_t)n * EE + sc4;
        else if (n < QDIM + KVDIM)   bptr[p] = Wk + (size_t)(n - QDIM) * EE + sc4;
        else                         bptr[p] = Wv + (size_t)(n - QDIM - KVDIM) * EE + sc4;
    }

    float acc[4][4][4];
    #pragma unroll
    for (int mt = 0; mt < 4; mt++)
        #pragma unroll
        for (int nt = 0; nt < 4; nt++)
            #pragma unroll
            for (int e = 0; e < 4; e++) acc[mt][nt][e] = 0.f;

    float4 ra[4], rb[4];
    #pragma unroll
    for (int p = 0; p < 4; p++) {
        ra[p] = *(const float4*)(aptr + (size_t)(32 * p) * EE);
        rb[p] = *(const float4*)(bptr[p]);
    }

    for (int k0 = 0; k0 < EE; k0 += 32) {
        __syncthreads();
        #pragma unroll
        for (int p = 0; p < 4; p++) {
            const int r = srow + 32 * p;
            unsigned* a = &As[r * GPAD + soff];
            a[0] = f2tf(ra[p].x); a[2] = f2tf(ra[p].y);
            a[4] = f2tf(ra[p].z); a[6] = f2tf(ra[p].w);
            unsigned* b = &Bs[r * GPAD + soff];
            b[0] = f2tf(rb[p].x); b[2] = f2tf(rb[p].y);
            b[4] = f2tf(rb[p].z); b[6] = f2tf(rb[p].w);
        }
        __syncthreads();
        if (k0 + 32 < EE) {
            #pragma unroll
            for (int p = 0; p < 4; p++) {
                ra[p] = *(const float4*)(aptr + (size_t)(32 * p) * EE + k0 + 32);
                rb[p] = *(const float4*)(bptr[p] + k0 + 32);
            }
        }
        #pragma unroll
        for (int ks = 0; ks < 4; ks++) {
            uint2 alo[4], ahi[4], bb[4];
            #pragma unroll
            for (int mt = 0; mt < 4; mt++) {
                alo[mt] = *(const uint2*)&As[(wm + mt * 16 + gy) * GPAD + ks * 8 + 2 * gx];
                ahi[mt] = *(const uint2*)&As[(wm + mt * 16 + gy + 8) * GPAD + ks * 8 + 2 * gx];
            }
            #pragma unroll
            for (int nt = 0; nt < 4; nt++)
                bb[nt] = *(const uint2*)&Bs[(wn + nt * 8 + gy) * GPAD + ks * 8 + 2 * gx];
            #pragma unroll
            for (int mt = 0; mt < 4; mt++)
                #pragma unroll
                for (int nt = 0; nt < 4; nt++)
                    mma8(acc[mt][nt], alo[mt].x, ahi[mt].x, alo[mt].y, ahi[mt].y,
                         bb[nt].x, bb[nt].y);
        }
    }

    #pragma unroll
    for (int mt = 0; mt < 4; mt++) {
        #pragma unroll
        for (int nt = 0; nt < 4; nt++) {
            const int row = bm + wm + mt * 16 + gy;
            const int col = bn + wn + nt * 8 + 2 * gx;
            *(float2*)qkv_ptr(row, col)     = make_float2(acc[mt][nt][0], acc[mt][nt][1]);
            *(float2*)qkv_ptr(row + 8, col) = make_float2(acc[mt][nt][2], acc[mt][nt][3]);
        }
    }
}

// ---------------------------------------------------------------------------
// GEMM 2: out = y (4096x1024) @ Wproj^T (1024x1024), tf32 mma
// ---------------------------------------------------------------------------
__global__ void __launch_bounds__(256) gemm_proj(
    const float* __restrict__ W, float* __restrict__ C)
{
    __shared__ unsigned As[128 * GPAD];
    __shared__ unsigned Bs[128 * GPAD];

    const int bm = blockIdx.y * 128;
    const int bn = blockIdx.x * 128;
    const int tid = threadIdx.x;
    const int lane = tid & 31;
    const int wid = tid >> 5;
    const int wm = (wid >> 2) * 64;
    const int wn = (wid & 3) * 32;
    const int gy = lane >> 2;
    const int gx = lane & 3;

    const int srow = tid >> 3;
    const int sc4  = (tid & 7) * 4;
    const int soff = (sc4 & ~7) + ((sc4 >> 2) & 1);

    const float* aptr = g_y + (size_t)(bm + srow) * EE + sc4;
    const float* bptr = W + (size_t)(bn + srow) * EE + sc4;

    float acc[4][4][4];
    #pragma unroll
    for (int mt = 0; mt < 4; mt++)
        #pragma unroll
        for (int nt = 0; nt < 4; nt++)
            #pragma unroll
            for (int e = 0; e < 4; e++) acc[mt][nt][e] = 0.f;

    float4 ra[4], rb[4];
    #pragma unroll
    for (int p = 0; p < 4; p++) {
        ra[p] = *(const float4*)(aptr + (size_t)(32 * p) * EE);
        rb[p] = *(const float4*)(bptr + (size_t)(32 * p) * EE);
    }

    for (int k0 = 0; k0 < EE; k0 += 32) {
        __syncthreads();
        #pragma unroll
        for (int p = 0; p < 4; p++) {
            const int r = srow + 32 * p;
            unsigned* a = &As[r * GPAD + soff];
            a[0] = f2tf(ra[p].x); a[2] = f2tf(ra[p].y);
            a[4] = f2tf(ra[p].z); a[6] = f2tf(ra[p].w);
            unsigned* b = &Bs[r * GPAD + soff];
            b[0] = f2tf(rb[p].x); b[2] = f2tf(rb[p].y);
            b[4] = f2tf(rb[p].z); b[6] = f2tf(rb[p].w);
        }
        __syncthreads();
        if (k0 + 32 < EE) {
            #pragma unroll
            for (int p = 0; p < 4; p++) {
                ra[p] = *(const float4*)(aptr + (size_t)(32 * p) * EE + k0 + 32);
                rb[p] = *(const float4*)(bptr + (size_t)(32 * p) * EE + k0 + 32);
            }
        }
        #pragma unroll
        for (int ks = 0; ks < 4; ks++) {
            uint2 alo[4], ahi[4], bb[4];
            #pragma unroll
            for (int mt = 0; mt < 4; mt++) {
                alo[mt] = *(const uint2*)&As[(wm + mt * 16 + gy) * GPAD + ks * 8 + 2 * gx];
                ahi[mt] = *(const uint2*)&As[(wm + mt * 16 + gy + 8) * GPAD + ks * 8 + 2 * gx];
            }
            #pragma unroll
            for (int nt = 0; nt < 4; nt++)
                bb[nt] = *(const uint2*)&Bs[(wn + nt * 8 + gy) * GPAD + ks * 8 + 2 * gx];
            #pragma unroll
            for (int mt = 0; mt < 4; mt++)
                #pragma unroll
                for (int nt = 0; nt < 4; nt++)
                    mma8(acc[mt][nt], alo[mt].x, ahi[mt].x, alo[mt].y, ahi[mt].y,
                         bb[nt].x, bb[nt].y);
        }
    }

    #pragma unroll
    for (int mt = 0; mt < 4; mt++) {
        #pragma unroll
        for (int nt = 0; nt < 4; nt++) {
            const int row = bm + wm + mt * 16 + gy;
            const int col = bn + wn + nt * 8 + 2 * gx;
            *(float2*)&C[(size_t)row * EE + col] =
                make_float2(acc[mt][nt][0], acc[mt][nt][1]);
            *(float2*)&C[(size_t)(row + 8) * EE + col] =
                make_float2(acc[mt][nt][2], acc[mt][nt][3]);
        }
    }
}

// ---------------------------------------------------------------------------
// Epilogue: RoPE + RMS-norm on q (16 heads) and k (4 heads); gated ve add
// on v (4 heads). One warp per (token, unit), unit in [0,24). (unchanged)
// ---------------------------------------------------------------------------
__global__ void __launch_bounds__(128) rope_gate(
    const float* __restrict__ X, const float* __restrict__ VE,
    const float* __restrict__ Cos, const float* __restrict__ Sin,
    const float* __restrict__ Wgate)
{
    const int gw = blockIdx.x * 4 + (threadIdx.x >> 5);
    const int lane = threadIdx.x & 31;
    const int token = gw / 24;
    const int unit = gw - token * 24;
    const int s = token & (SS - 1);

    if (unit >= 20) {  // v gate
        const int kv = unit - 20;
        const float* xr = X + (size_t)token * EE;
        float g = 0.f;
        #pragma unroll
        for (int c = 0; c < GCH; c++) g = fmaf(xr[c], Wgate[kv * GCH + c], g);
        g = 3.f / (1.f + __expf(-g));
        float* vb = g_v + (size_t)token * KVDIM + kv * HDD;
        const float* veb = VE + (size_t)token * KVDIM + kv * HDD;
        vb[lane]      += g * veb[lane];
        vb[lane + 32] += g * veb[lane + 32];
        return;
    }

    float* base = (unit < NHH)
        ? g_q + (size_t)token * QDIM + unit * HDD
        : g_k + (size_t)token * KVDIM + (unit - NHH) * HDD;

    const float c  = Cos[s * 32 + lane];
    const float sn = Sin[s * 32 + lane];
    const float x1 = base[lane];
    const float x2 = base[lane + 32];
    const float o1 =  x1 * c + x2 * sn;
    const float o2 = -x1 * sn + x2 * c;
    float ssum = o1 * o1 + o2 * o2;
    #pragma unroll
    for (int off = 16; off; off >>= 1)
        ssum += __shfl_xor_sync(0xffffffffu, ssum, off);
    const float inv = rsqrtf(ssum * (1.f / 64.f) + 1.1920928955078125e-07f) * 1.2f;
    base[lane]      = o1 * inv;
    base[lane + 32] = o2 * inv;
}

// ---------------------------------------------------------------------------
// Flash attention, GQA-shared: one block = one kv-head x 32 q-positions x all
// 4 q-heads = 128 virtual q-rows. 8 warps, 16-row bands. KV tiles of 64
// positions, register-prefetch double buffered. Interleaved smem layout ->
// LDS.64 fragments. Q buffer reused for P (warp-private bands).
// smem: Qs 128x72 | Ks 64x72 | Vs 64x72 = 73728 B (dynamic)
// ---------------------------------------------------------------------------
#define APAD 72
#define ATTN_SMEM_BYTES (256 * APAD * 4)

__global__ void __launch_bounds__(256) attn_kernel()
{
    extern __shared__ unsigned sm[];
    unsigned* Qs = sm;                  // reused as P after frag extraction
    unsigned* Ks = sm + 128 * APAD;
    unsigned* Vs = sm + 192 * APAD;

    const int qp  = blockIdx.x;         // q position tile of 32 (64)
    const int hkv = blockIdx.y;         // kv head (4)
    const int b   = blockIdx.z;         // batch (2)
    const int q0  = qp * 32;
    const int tid = threadIdx.x;
    const int lane = tid & 31;
    const int wid = tid >> 5;           // 0..7
    const int gy = lane >> 2;
    const int gx = lane & 3;
    const int r0 = wid * 16 + gy;       // virtual row (head*32 + pos offset)
    const int h  = hkv * 4 + (wid >> 1);
    const int pos0 = q0 + ((wid & 1) * 16 + gy);
    const int pos1 = pos0 + 8;

    // Stage Q (scaled by 1/8), interleaved tf32
    for (int idx = tid; idx < 128 * 16; idx += 256) {
        const int r = idx >> 4, c4 = (idx & 15) * 4;
        const float4 v = *(const float4*)&g_q[(size_t)(b * SS + q0 + (r & 31)) * QDIM
                                              + (hkv * 4 + (r >> 5)) * HDD + c4];
        unsigned* q = &Qs[r * APAD + (c4 & ~7) + ((c4 >> 2) & 1)];
        q[0] = f2tf(v.x * 0.125f); q[2] = f2tf(v.y * 0.125f);
        q[4] = f2tf(v.z * 0.125f); q[6] = f2tf(v.w * 0.125f);
    }
    __syncthreads();

    // Extract Q fragments (reused across all kv tiles)
    unsigned qa[8][4];
    #pragma unroll
    for (int ks = 0; ks < 8; ks++) {
        const uint2 lo = *(const uint2*)&Qs[r0 * APAD + ks * 8 + 2 * gx];
        const uint2 hi = *(const uint2*)&Qs[(r0 + 8) * APAD + ks * 8 + 2 * gx];
        qa[ks][0] = lo.x; qa[ks][1] = hi.x; qa[ks][2] = lo.y; qa[ks][3] = hi.y;
    }

    float Oa[8][4];
    #pragma unroll
    for (int nt = 0; nt < 8; nt++)
        #pragma unroll
        for (int e = 0; e < 4; e++) Oa[nt][e] = 0.f;
    float m0 = -1e30f, m1 = -1e30f, l0 = 0.f, l1 = 0.f;

    const int ntiles = (q0 + 95) >> 6;
    const int c4s  = (tid & 15) * 4;
    const int rb   = tid >> 4;                         // 0..15
    const int soff = (c4s & ~7) + ((c4s >> 2) & 1);
    const int pg   = (gy & 3) * 2 + (gy >> 2);         // interleaved col of gy
    const int pc0  = ((2 * gx) & 3) * 2 + (((2 * gx) >> 2) & 1);
    const int pc1  = ((2 * gx + 1) & 3) * 2 + (((2 * gx + 1) >> 2) & 1);
    const float* kp = g_k + (size_t)(b * SS) * KVDIM + hkv * HDD + c4s;
    const float* vp = g_v + (size_t)(b * SS) * KVDIM + hkv * HDD + c4s;

    float4 rk[4], rv[4];
    #pragma unroll
    for (int c = 0; c < 4; c++) {
        const size_t ro = (size_t)(rb + 16 * c) * KVDIM;
        rk[c] = *(const float4*)(kp + ro);
        rv[c] = *(const float4*)(vp + ro);
    }

    for (int j = 0; j < ntiles; j++) {
        __syncthreads();   // prior tile's consumers (incl. P in Qs) done
        #pragma unroll
        for (int c = 0; c < 4; c++) {
            unsigned* kd = &Ks[(rb + 16 * c) * APAD + soff];
            kd[0] = f2tf(rk[c].x); kd[2] = f2tf(rk[c].y);
            kd[4] = f2tf(rk[c].z); kd[6] = f2tf(rk[c].w);
            unsigned* vd = &Vs[(rb + 16 * c) * APAD + soff];
            vd[0] = f2tf(rv[c].x); vd[2] = f2tf(rv[c].y);
            vd[4] = f2tf(rv[c].z); vd[6] = f2tf(rv[c].w);
        }
        __syncthreads();
        if (j + 1 < ntiles) {  // prefetch next tile (latency hidden by mmas)
            const size_t tb = (size_t)((j + 1) * 64) * KVDIM;
            #pragma unroll
            for (int c = 0; c < 4; c++) {
                const size_t ro = tb + (size_t)(rb + 16 * c) * KVDIM;
                rk[c] = *(const float4*)(kp + ro);
                rv[c] = *(const float4*)(vp + ro);
            }
        }

        // S = Q K^T
        float sf[8][4];
        #pragma unroll
        for (int nt = 0; nt < 8; nt++)
            #pragma unroll
            for (int e = 0; e < 4; e++) sf[nt][e] = 0.f;
        #pragma unroll
        for (int ks = 0; ks < 8; ks++) {
            #pragma unroll
            for (int nt = 0; nt < 8; nt++) {
                const uint2 kb = *(const uint2*)&Ks[(nt * 8 + gy) * APAD + ks * 8 + 2 * gx];
                mma8(sf[nt], qa[ks][0], qa[ks][1], qa[ks][2], qa[ks][3], kb.x, kb.y);
            }
        }

        // causal mask (last tile only); scale folded into Q
        if (j == ntiles - 1) {
            #pragma unroll
            for (int nt = 0; nt < 8; nt++) {
                const int c = j * 64 + nt * 8 + 2 * gx;
                if (c     > pos0) sf[nt][0] = -1e30f;
                if (c + 1 > pos0) sf[nt][1] = -1e30f;
                if (c     > pos1) sf[nt][2] = -1e30f;
                if (c + 1 > pos1) sf[nt][3] = -1e30f;
            }
        }

        // online softmax (rows pos0: elems 0,1 / pos1: elems 2,3)
        float mx0 = -1e30f, mx1 = -1e30f;
        #pragma unroll
        for (int nt = 0; nt < 8; nt++) {
            mx0 = fmaxf(mx0, fmaxf(sf[nt][0], sf[nt][1]));
            mx1 = fmaxf(mx1, fmaxf(sf[nt][2], sf[nt][3]));
        }
        mx0 = fmaxf(mx0, __shfl_xor_sync(0xffffffffu, mx0, 1));
        mx0 = fmaxf(mx0, __shfl_xor_sync(0xffffffffu, mx0, 2));
        mx1 = fmaxf(mx1, __shfl_xor_sync(0xffffffffu, mx1, 1));
        mx1 = fmaxf(mx1, __shfl_xor_sync(0xffffffffu, mx1, 2));
        const float mn0 = fmaxf(m0, mx0);
        const float mn1 = fmaxf(m1, mx1);
        float ps0 = 0.f, ps1 = 0.f;
        #pragma unroll
        for (int nt = 0; nt < 8; nt++) {
            sf[nt][0] = __expf(sf[nt][0] - mn0);
            sf[nt][1] = __expf(sf[nt][1] - mn0);
            sf[nt][2] = __expf(sf[nt][2] - mn1);
            sf[nt][3] = __expf(sf[nt][3] - mn1);
            ps0 += sf[nt][0] + sf[nt][1];
            ps1 += sf[nt][2] + sf[nt][3];
        }
        ps0 += __shfl_xor_sync(0xffffffffu, ps0, 1);
        ps0 += __shfl_xor_sync(0xffffffffu, ps0, 2);
        ps1 += __shfl_xor_sync(0xffffffffu, ps1, 1);
        ps1 += __shfl_xor_sync(0xffffffffu, ps1, 2);
        const float scl0 = __expf(m0 - mn0);
        const float scl1 = __expf(m1 - mn1);
        l0 = l0 * scl0 + ps0;
        l1 = l1 * scl1 + ps1;
        m0 = mn0; m1 = mn1;

        // store P (interleaved) into Q buffer: warp-private 16-row band
        #pragma unroll
        for (int nt = 0; nt < 8; nt++) {
            const int a = r0 * APAD + nt * 8;
            Qs[a + pc0] = f2tf(sf[nt][0]);
            Qs[a + pc1] = f2tf(sf[nt][1]);
            Qs[a + 8 * APAD + pc0] = f2tf(sf[nt][2]);
            Qs[a + 8 * APAD + pc1] = f2tf(sf[nt][3]);
        }
        __syncwarp();

        // rescale O
        #pragma unroll
        for (int nt = 0; nt < 8; nt++) {
            Oa[nt][0] *= scl0; Oa[nt][1] *= scl0;
            Oa[nt][2] *= scl1; Oa[nt][3] *= scl1;
        }

        // O += P V
        #pragma unroll
        for (int ks = 0; ks < 8; ks++) {
            const uint2 plo = *(const uint2*)&Qs[r0 * APAD + ks * 8 + 2 * gx];
            const uint2 phi = *(const uint2*)&Qs[(r0 + 8) * APAD + ks * 8 + 2 * gx];
            #pragma unroll
            for (int nt = 0; nt < 8; nt++) {
                const int vb = (ks * 8 + gx) * APAD + nt * 8 + pg;
                mma8(Oa[nt], plo.x, phi.x, plo.y, phi.y, Vs[vb], Vs[vb + 4 * APAD]);
            }
        }
    }

    // epilogue: normalize and store
    const float inv0 = 1.f / l0;
    const float inv1 = 1.f / l1;
    const size_t row0 = (size_t)(b * SS + pos0) * QDIM + h * HDD;
    const size_t row1 = (size_t)(b * SS + pos1) * QDIM + h * HDD;
    #pragma unroll
    for (int nt = 0; nt < 8; nt++) {
        const int col = nt * 8 + 2 * gx;
        *(float2*)&g_y[row0 + col] = make_float2(Oa[nt][0] * inv0, Oa[nt][1] * inv0);
        *(float2*)&g_y[row1 + col] = make_float2(Oa[nt][2] * inv1, Oa[nt][3] * inv1);
    }
}

// ---------------------------------------------------------------------------
// Launch: qkv GEMM -> rope/rms/gate -> flash attention -> proj GEMM
// Inputs: 0 x, 1 ve, 2 cos, 3 sin, 4 attn_mask(unused), 5 Wq, 6 Wk, 7 Wv,
//         8 Wproj, 9 Wgate. Output: float32 (B,S,E).
// ---------------------------------------------------------------------------
extern "C" void kernel_launch(void* const* d_in, const int* in_sizes, int n_in,
                              void* d_out, int out_size)
{
    const float* x     = (const float*)d_in[0];
    const float* ve    = (const float*)d_in[1];
    const float* cosb  = (const float*)d_in[2];
    const float* sinb  = (const float*)d_in[3];
    const float* Wq    = (const float*)d_in[5];
    const float* Wk    = (const float*)d_in[6];
    const float* Wv    = (const float*)d_in[7];
    const float* Wproj = (const float*)d_in[8];
    const float* Wgate = (const float*)d_in[9];
    float* out = (float*)d_out;

    (void)in_sizes; (void)n_in; (void)out_size;

    cudaFuncSetAttribute(attn_kernel,
                         cudaFuncAttributeMaxDynamicSharedMemorySize,
                         ATTN_SMEM_BYTES);

    // 1) QKV projection: grid (1536/128, 4096/128)
    gemm_qkv<<<dim3(12, 32), 256>>>(x, Wq, Wk, Wv);

    // 2) RoPE + RMS + gated-ve
    rope_gate<<<(MM * 24) / 4, 128>>>(x, ve, cosb, sinb, Wgate);

    // 3) Flash attention (GQA-shared): (pos-tiles of 32, kv heads, batch)
    attn_kernel<<<dim3(SS / 32, NKVV, BB), 256, ATTN_SMEM_BYTES>>>();

    // 4) Output projection: grid (1024/128, 4096/128)
    gemm_proj<<<dim3(8, 32), 256>>>(Wproj, out);
}

// round 13
// speedup vs baseline: 1.0953x; 1.0953x over previous
#include <cuda_runtime.h>
#include <math.h>
#include <stdint.h>

// Problem constants
#define BB   2
#define SS   2048
#define EE   1024
#define NHH  16
#define NKVV 4
#define HDD  64
#define GCH  12
#define MM   (BB * SS)        // 4096 tokens
#define QDIM (NHH * HDD)      // 1024
#define KVDIM (NKVV * HDD)    // 256

// Scratch (device globals: allocation-free rule)
__device__ float g_q[MM * QDIM];    // 16 MB
__device__ float g_k[MM * KVDIM];   //  4 MB
__device__ float g_v[MM * KVDIM];   //  4 MB
__device__ float g_y[MM * QDIM];    // 16 MB

// ---------------------------------------------------------------------------
// tf32 helpers
// ---------------------------------------------------------------------------
__device__ __forceinline__ unsigned f2tf(float x) {
    unsigned u;
    asm("cvt.rna.tf32.f32 %0, %1;" : "=r"(u) : "f"(x));
    return u;
}

// D += A(16x8) * B(8x8), tf32 inputs, f32 accumulate
__device__ __forceinline__ void mma8(float* c,
                                     unsigned a0, unsigned a1, unsigned a2, unsigned a3,
                                     unsigned b0, unsigned b1) {
    asm volatile(
        "mma.sync.aligned.m16n8k8.row.col.f32.tf32.tf32.f32 "
        "{%0,%1,%2,%3},{%4,%5,%6,%7},{%8,%9},{%0,%1,%2,%3};"
        : "+f"(c[0]), "+f"(c[1]), "+f"(c[2]), "+f"(c[3])
        : "r"(a0), "r"(a1), "r"(a2), "r"(a3), "r"(b0), "r"(b1));
}

__device__ __forceinline__ float* qkv_ptr(int row, int col) {
    if (col < QDIM)         return &g_q[(size_t)row * QDIM + col];
    if (col < QDIM + KVDIM) return &g_k[(size_t)row * KVDIM + (col - QDIM)];
    return &g_v[(size_t)row * KVDIM + (col - QDIM - KVDIM)];
}

// Pair-interleaved smem layout: within each 8-word group, logical col c sits
// at physical (c&~7) + 2*(c&3) + ((c>>2)&1), so (c, c+4) pairs are adjacent
// and fragment loads become one LDS.64. Pad strides chosen == 8 (mod 32) so
// the 64-bit loads are phase-conflict-free.

// ---------------------------------------------------------------------------
// GEMM 1: [q|k|v] = X (4096x1024) @ [Wq;Wk;Wv]^T (1536x1024), tf32 mma
// 128x128 block, k-chunk 32, 8 warps (2x4), warp tile 64x32, reg prefetch.
// __launch_bounds__(256, 2): cap regs at 128 so 2 blocks stay resident
// (round-8 regression: 130 regs -> 1 block/SM -> tensor pipe starved).
// ---------------------------------------------------------------------------
#define GPAD 40

__global__ void __launch_bounds__(256, 2) gemm_qkv(
    const float* __restrict__ X,
    const float* __restrict__ Wq,
    const float* __restrict__ Wk,
    const float* __restrict__ Wv)
{
    __shared__ unsigned As[128 * GPAD];
    __shared__ unsigned Bs[128 * GPAD];

    const int bm = blockIdx.y * 128;
    const int bn = blockIdx.x * 128;
    const int tid = threadIdx.x;
    const int lane = tid & 31;
    const int wid = tid >> 5;
    const int wm = (wid >> 2) * 64;   // 0 or 64
    const int wn = (wid & 3) * 32;    // 0..96
    const int gy = lane >> 2;         // 0..7
    const int gx = lane & 3;          // 0..3

    const int srow = tid >> 3;          // base row 0..31 (stride 32 via p)
    const int sc4  = (tid & 7) * 4;     // logical col 0,4,..,28
    const int soff = (sc4 & ~7) + ((sc4 >> 2) & 1);  // interleaved store base

    const float* aptr = X + (size_t)(bm + srow) * EE + sc4;
    const float* bptr[4];
    #pragma unroll
    for (int p = 0; p < 4; p++) {
        const int n = bn + srow + 32 * p;
        if (n < QDIM)                bptr[p] = Wq + (size_t)n * EE + sc4;
        else if (n < QDIM + KVDIM)   bptr[p] = Wk + (size_t)(n - QDIM) * EE + sc4;
        else                         bptr[p] = Wv + (size_t)(n - QDIM - KVDIM) * EE + sc4;
    }

    float acc[4][4][4];
    #pragma unroll
    for (int mt = 0; mt < 4; mt++)
        #pragma unroll
        for (int nt = 0; nt < 4; nt++)
            #pragma unroll
            for (int e = 0; e < 4; e++) acc[mt][nt][e] = 0.f;

    float4 ra[4], rb[4];
    #pragma unroll
    for (int p = 0; p < 4; p++) {
        ra[p] = *(const float4*)(aptr + (size_t)(32 * p) * EE);
        rb[p] = *(const float4*)(bptr[p]);
    }

    for (int k0 = 0; k0 < EE; k0 += 32) {
        __syncthreads();
        #pragma unroll
        for (int p = 0; p < 4; p++) {
            const int r = srow + 32 * p;
            unsigned* a = &As[r * GPAD + soff];
            a[0] = f2tf(ra[p].x); a[2] = f2tf(ra[p].y);
            a[4] = f2tf(ra[p].z); a[6] = f2tf(ra[p].w);
            unsigned* b = &Bs[r * GPAD + soff];
            b[0] = f2tf(rb[p].x); b[2] = f2tf(rb[p].y);
            b[4] = f2tf(rb[p].z); b[6] = f2tf(rb[p].w);
        }
        __syncthreads();
        if (k0 + 32 < EE) {
            #pragma unroll
            for (int p = 0; p < 4; p++) {
                ra[p] = *(const float4*)(aptr + (size_t)(32 * p) * EE + k0 + 32);
                rb[p] = *(const float4*)(bptr[p] + k0 + 32);
            }
        }
        #pragma unroll
        for (int ks = 0; ks < 4; ks++) {
            uint2 alo[4], ahi[4], bb[4];
            #pragma unroll
            for (int mt = 0; mt < 4; mt++) {
                alo[mt] = *(const uint2*)&As[(wm + mt * 16 + gy) * GPAD + ks * 8 + 2 * gx];
                ahi[mt] = *(const uint2*)&As[(wm + mt * 16 + gy + 8) * GPAD + ks * 8 + 2 * gx];
            }
            #pragma unroll
            for (int nt = 0; nt < 4; nt++)
                bb[nt] = *(const uint2*)&Bs[(wn + nt * 8 + gy) * GPAD + ks * 8 + 2 * gx];
            #pragma unroll
            for (int mt = 0; mt < 4; mt++)
                #pragma unroll
                for (int nt = 0; nt < 4; nt++)
                    mma8(acc[mt][nt], alo[mt].x, ahi[mt].x, alo[mt].y, ahi[mt].y,
                         bb[nt].x, bb[nt].y);
        }
    }

    #pragma unroll
    for (int mt = 0; mt < 4; mt++) {
        #pragma unroll
        for (int nt = 0; nt < 4; nt++) {
            const int row = bm + wm + mt * 16 + gy;
            const int col = bn + wn + nt * 8 + 2 * gx;
            *(float2*)qkv_ptr(row, col)     = make_float2(acc[mt][nt][0], acc[mt][nt][1]);
            *(float2*)qkv_ptr(row + 8, col) = make_float2(acc[mt][nt][2], acc[mt][nt][3]);
        }
    }
}

// ---------------------------------------------------------------------------
// GEMM 2: out = y (4096x1024) @ Wproj^T (1024x1024), tf32 mma
// ---------------------------------------------------------------------------
__global__ void __launch_bounds__(256, 2) gemm_proj(
    const float* __restrict__ W, float* __restrict__ C)
{
    __shared__ unsigned As[128 * GPAD];
    __shared__ unsigned Bs[128 * GPAD];

    const int bm = blockIdx.y * 128;
    const int bn = blockIdx.x * 128;
    const int tid = threadIdx.x;
    const int lane = tid & 31;
    const int wid = tid >> 5;
    const int wm = (wid >> 2) * 64;
    const int wn = (wid & 3) * 32;
    const int gy = lane >> 2;
    const int gx = lane & 3;

    const int srow = tid >> 3;
    const int sc4  = (tid & 7) * 4;
    const int soff = (sc4 & ~7) + ((sc4 >> 2) & 1);

    const float* aptr = g_y + (size_t)(bm + srow) * EE + sc4;
    const float* bptr = W + (size_t)(bn + srow) * EE + sc4;

    float acc[4][4][4];
    #pragma unroll
    for (int mt = 0; mt < 4; mt++)
        #pragma unroll
        for (int nt = 0; nt < 4; nt++)
            #pragma unroll
            for (int e = 0; e < 4; e++) acc[mt][nt][e] = 0.f;

    float4 ra[4], rb[4];
    #pragma unroll
    for (int p = 0; p < 4; p++) {
        ra[p] = *(const float4*)(aptr + (size_t)(32 * p) * EE);
        rb[p] = *(const float4*)(bptr + (size_t)(32 * p) * EE);
    }

    for (int k0 = 0; k0 < EE; k0 += 32) {
        __syncthreads();
        #pragma unroll
        for (int p = 0; p < 4; p++) {
            const int r = srow + 32 * p;
            unsigned* a = &As[r * GPAD + soff];
            a[0] = f2tf(ra[p].x); a[2] = f2tf(ra[p].y);
            a[4] = f2tf(ra[p].z); a[6] = f2tf(ra[p].w);
            unsigned* b = &Bs[r * GPAD + soff];
            b[0] = f2tf(rb[p].x); b[2] = f2tf(rb[p].y);
            b[4] = f2tf(rb[p].z); b[6] = f2tf(rb[p].w);
        }
        __syncthreads();
        if (k0 + 32 < EE) {
            #pragma unroll
            for (int p = 0; p < 4; p++) {
                ra[p] = *(const float4*)(aptr + (size_t)(32 * p) * EE + k0 + 32);
                rb[p] = *(const float4*)(bptr + (size_t)(32 * p) * EE + k0 + 32);
            }
        }
        #pragma unroll
        for (int ks = 0; ks < 4; ks++) {
            uint2 alo[4], ahi[4], bb[4];
            #pragma unroll
            for (int mt = 0; mt < 4; mt++) {
                alo[mt] = *(const uint2*)&As[(wm + mt * 16 + gy) * GPAD + ks * 8 + 2 * gx];
                ahi[mt] = *(const uint2*)&As[(wm + mt * 16 + gy + 8) * GPAD + ks * 8 + 2 * gx];
            }
            #pragma unroll
            for (int nt = 0; nt < 4; nt++)
                bb[nt] = *(const uint2*)&Bs[(wn + nt * 8 + gy) * GPAD + ks * 8 + 2 * gx];
            #pragma unroll
            for (int mt = 0; mt < 4; mt++)
                #pragma unroll
                for (int nt = 0; nt < 4; nt++)
                    mma8(acc[mt][nt], alo[mt].x, ahi[mt].x, alo[mt].y, ahi[mt].y,
                         bb[nt].x, bb[nt].y);
        }
    }

    #pragma unroll
    for (int mt = 0; mt < 4; mt++) {
        #pragma unroll
        for (int nt = 0; nt < 4; nt++) {
            const int row = bm + wm + mt * 16 + gy;
            const int col = bn + wn + nt * 8 + 2 * gx;
            *(float2*)&C[(size_t)row * EE + col] =
                make_float2(acc[mt][nt][0], acc[mt][nt][1]);
            *(float2*)&C[(size_t)(row + 8) * EE + col] =
                make_float2(acc[mt][nt][2], acc[mt][nt][3]);
        }
    }
}

// ---------------------------------------------------------------------------
// Epilogue: RoPE + RMS-norm on q (16 heads) and k (4 heads); gated ve add
// on v (4 heads). One warp per (token, unit), unit in [0,24). (unchanged)
// ---------------------------------------------------------------------------
__global__ void __launch_bounds__(128) rope_gate(
    const float* __restrict__ X, const float* __restrict__ VE,
    const float* __restrict__ Cos, const float* __restrict__ Sin,
    const float* __restrict__ Wgate)
{
    const int gw = blockIdx.x * 4 + (threadIdx.x >> 5);
    const int lane = threadIdx.x & 31;
    const int token = gw / 24;
    const int unit = gw - token * 24;
    const int s = token & (SS - 1);

    if (unit >= 20) {  // v gate
        const int kv = unit - 20;
        const float* xr = X + (size_t)token * EE;
        float g = 0.f;
        #pragma unroll
        for (int c = 0; c < GCH; c++) g = fmaf(xr[c], Wgate[kv * GCH + c], g);
        g = 3.f / (1.f + __expf(-g));
        float* vb = g_v + (size_t)token * KVDIM + kv * HDD;
        const float* veb = VE + (size_t)token * KVDIM + kv * HDD;
        vb[lane]      += g * veb[lane];
        vb[lane + 32] += g * veb[lane + 32];
        return;
    }

    float* base = (unit < NHH)
        ? g_q + (size_t)token * QDIM + unit * HDD
        : g_k + (size_t)token * KVDIM + (unit - NHH) * HDD;

    const float c  = Cos[s * 32 + lane];
    const float sn = Sin[s * 32 + lane];
    const float x1 = base[lane];
    const float x2 = base[lane + 32];
    const float o1 =  x1 * c + x2 * sn;
    const float o2 = -x1 * sn + x2 * c;
    float ssum = o1 * o1 + o2 * o2;
    #pragma unroll
    for (int off = 16; off; off >>= 1)
        ssum += __shfl_xor_sync(0xffffffffu, ssum, off);
    const float inv = rsqrtf(ssum * (1.f / 64.f) + 1.1920928955078125e-07f) * 1.2f;
    base[lane]      = o1 * inv;
    base[lane + 32] = o2 * inv;
}

// ---------------------------------------------------------------------------
// Flash attention, GQA-shared: one block = one kv-head x 32 q-positions x all
// 4 q-heads = 128 virtual q-rows. 8 warps, 16-row bands. KV tiles of 64
// positions, register-prefetch double buffered. Interleaved smem layout ->
// LDS.64 fragments. Q buffer reused for P (warp-private bands).
// smem: Qs 128x72 | Ks 64x72 | Vs 64x72 = 73728 B (dynamic)
// ---------------------------------------------------------------------------
#define APAD 72
#define ATTN_SMEM_BYTES (256 * APAD * 4)

__global__ void __launch_bounds__(256) attn_kernel()
{
    extern __shared__ unsigned sm[];
    unsigned* Qs = sm;                  // reused as P after frag extraction
    unsigned* Ks = sm + 128 * APAD;
    unsigned* Vs = sm + 192 * APAD;

    const int qp  = blockIdx.x;         // q position tile of 32 (64)
    const int hkv = blockIdx.y;         // kv head (4)
    const int b   = blockIdx.z;         // batch (2)
    const int q0  = qp * 32;
    const int tid = threadIdx.x;
    const int lane = tid & 31;
    const int wid = tid >> 5;           // 0..7
    const int gy = lane >> 2;
    const int gx = lane & 3;
    const int r0 = wid * 16 + gy;       // virtual row (head*32 + pos offset)
    const int h  = hkv * 4 + (wid >> 1);
    const int pos0 = q0 + ((wid & 1) * 16 + gy);
    const int pos1 = pos0 + 8;

    // Stage Q (scaled by 1/8), interleaved tf32
    for (int idx = tid; idx < 128 * 16; idx += 256) {
        const int r = idx >> 4, c4 = (idx & 15) * 4;
        const float4 v = *(const float4*)&g_q[(size_t)(b * SS + q0 + (r & 31)) * QDIM
                                              + (hkv * 4 + (r >> 5)) * HDD + c4];
        unsigned* q = &Qs[r * APAD + (c4 & ~7) + ((c4 >> 2) & 1)];
        q[0] = f2tf(v.x * 0.125f); q[2] = f2tf(v.y * 0.125f);
        q[4] = f2tf(v.z * 0.125f); q[6] = f2tf(v.w * 0.125f);
    }
    __syncthreads();

    // Extract Q fragments (reused across all kv tiles)
    unsigned qa[8][4];
    #pragma unroll
    for (int ks = 0; ks < 8; ks++) {
        const uint2 lo = *(const uint2*)&Qs[r0 * APAD + ks * 8 + 2 * gx];
        const uint2 hi = *(const uint2*)&Qs[(r0 + 8) * APAD + ks * 8 + 2 * gx];
        qa[ks][0] = lo.x; qa[ks][1] = hi.x; qa[ks][2] = lo.y; qa[ks][3] = hi.y;
    }

    float Oa[8][4];
    #pragma unroll
    for (int nt = 0; nt < 8; nt++)
        #pragma unroll
        for (int e = 0; e < 4; e++) Oa[nt][e] = 0.f;
    float m0 = -1e30f, m1 = -1e30f, l0 = 0.f, l1 = 0.f;

    const int ntiles = (q0 + 95) >> 6;
    const int c4s  = (tid & 15) * 4;
    const int rb   = tid >> 4;                         // 0..15
    const int soff = (c4s & ~7) + ((c4s >> 2) & 1);
    const int pg   = (gy & 3) * 2 + (gy >> 2);         // interleaved col of gy
    const int pc0  = ((2 * gx) & 3) * 2 + (((2 * gx) >> 2) & 1);
    const int pc1  = ((2 * gx + 1) & 3) * 2 + (((2 * gx + 1) >> 2) & 1);
    const float* kp = g_k + (size_t)(b * SS) * KVDIM + hkv * HDD + c4s;
    const float* vp = g_v + (size_t)(b * SS) * KVDIM + hkv * HDD + c4s;

    float4 rk[4], rv[4];
    #pragma unroll
    for (int c = 0; c < 4; c++) {
        const size_t ro = (size_t)(rb + 16 * c) * KVDIM;
        rk[c] = *(const float4*)(kp + ro);
        rv[c] = *(const float4*)(vp + ro);
    }

    for (int j = 0; j < ntiles; j++) {
        __syncthreads();   // prior tile's consumers (incl. P in Qs) done
        #pragma unroll
        for (int c = 0; c < 4; c++) {
            unsigned* kd = &Ks[(rb + 16 * c) * APAD + soff];
            kd[0] = f2tf(rk[c].x); kd[2] = f2tf(rk[c].y);
            kd[4] = f2tf(rk[c].z); kd[6] = f2tf(rk[c].w);
            unsigned* vd = &Vs[(rb + 16 * c) * APAD + soff];
            vd[0] = f2tf(rv[c].x); vd[2] = f2tf(rv[c].y);
            vd[4] = f2tf(rv[c].z); vd[6] = f2tf(rv[c].w);
        }
        __syncthreads();
        if (j + 1 < ntiles) {  // prefetch next tile (latency hidden by mmas)
            const size_t tb = (size_t)((j + 1) * 64) * KVDIM;
            #pragma unroll
            for (int c = 0; c < 4; c++) {
                const size_t ro = tb + (size_t)(rb + 16 * c) * KVDIM;
                rk[c] = *(const float4*)(kp + ro);
                rv[c] = *(const float4*)(vp + ro);
            }
        }

        // S = Q K^T
        float sf[8][4];
        #pragma unroll
        for (int nt = 0; nt < 8; nt++)
            #pragma unroll
            for (int e = 0; e < 4; e++) sf[nt][e] = 0.f;
        #pragma unroll
        for (int ks = 0; ks < 8; ks++) {
            #pragma unroll
            for (int nt = 0; nt < 8; nt++) {
                const uint2 kb = *(const uint2*)&Ks[(nt * 8 + gy) * APAD + ks * 8 + 2 * gx];
                mma8(sf[nt], qa[ks][0], qa[ks][1], qa[ks][2], qa[ks][3], kb.x, kb.y);
            }
        }

        // causal mask (last tile only); scale folded into Q
        if (j == ntiles - 1) {
            #pragma unroll
            for (int nt = 0; nt < 8; nt++) {
                const int c = j * 64 + nt * 8 + 2 * gx;
                if (c     > pos0) sf[nt][0] = -1e30f;
                if (c + 1 > pos0) sf[nt][1] = -1e30f;
                if (c     > pos1) sf[nt][2] = -1e30f;
                if (c + 1 > pos1) sf[nt][3] = -1e30f;
            }
        }

        // online softmax (rows pos0: elems 0,1 / pos1: elems 2,3)
        float mx0 = -1e30f, mx1 = -1e30f;
        #pragma unroll
        for (int nt = 0; nt < 8; nt++) {
            mx0 = fmaxf(mx0, fmaxf(sf[nt][0], sf[nt][1]));
            mx1 = fmaxf(mx1, fmaxf(sf[nt][2], sf[nt][3]));
        }
        mx0 = fmaxf(mx0, __shfl_xor_sync(0xffffffffu, mx0, 1));
        mx0 = fmaxf(mx0, __shfl_xor_sync(0xffffffffu, mx0, 2));
        mx1 = fmaxf(mx1, __shfl_xor_sync(0xffffffffu, mx1, 1));
        mx1 = fmaxf(mx1, __shfl_xor_sync(0xffffffffu, mx1, 2));
        const float mn0 = fmaxf(m0, mx0);
        const float mn1 = fmaxf(m1, mx1);
        float ps0 = 0.f, ps1 = 0.f;
        #pragma unroll
        for (int nt = 0; nt < 8; nt++) {
            sf[nt][0] = __expf(sf[nt][0] - mn0);
            sf[nt][1] = __expf(sf[nt][1] - mn0);
            sf[nt][2] = __expf(sf[nt][2] - mn1);
            sf[nt][3] = __expf(sf[nt][3] - mn1);
            ps0 += sf[nt][0] + sf[nt][1];
            ps1 += sf[nt][2] + sf[nt][3];
        }
        ps0 += __shfl_xor_sync(0xffffffffu, ps0, 1);
        ps0 += __shfl_xor_sync(0xffffffffu, ps0, 2);
        ps1 += __shfl_xor_sync(0xffffffffu, ps1, 1);
        ps1 += __shfl_xor_sync(0xffffffffu, ps1, 2);
        const float scl0 = __expf(m0 - mn0);
        const float scl1 = __expf(m1 - mn1);
        l0 = l0 * scl0 + ps0;
        l1 = l1 * scl1 + ps1;
        m0 = mn0; m1 = mn1;

        // store P (interleaved) into Q buffer: warp-private 16-row band
        #pragma unroll
        for (int nt = 0; nt < 8; nt++) {
            const int a = r0 * APAD + nt * 8;
            Qs[a + pc0] = f2tf(sf[nt][0]);
            Qs[a + pc1] = f2tf(sf[nt][1]);
            Qs[a + 8 * APAD + pc0] = f2tf(sf[nt][2]);
            Qs[a + 8 * APAD + pc1] = f2tf(sf[nt][3]);
        }
        __syncwarp();

        // rescale O
        #pragma unroll
        for (int nt = 0; nt < 8; nt++) {
            Oa[nt][0] *= scl0; Oa[nt][1] *= scl0;
            Oa[nt][2] *= scl1; Oa[nt][3] *= scl1;
        }

        // O += P V
        #pragma unroll
        for (int ks = 0; ks < 8; ks++) {
            const uint2 plo = *(const uint2*)&Qs[r0 * APAD + ks * 8 + 2 * gx];
            const uint2 phi = *(const uint2*)&Qs[(r0 + 8) * APAD + ks * 8 + 2 * gx];
            #pragma unroll
            for (int nt = 0; nt < 8; nt++) {
                const int vb = (ks * 8 + gx) * APAD + nt * 8 + pg;
                mma8(Oa[nt], plo.x, phi.x, plo.y, phi.y, Vs[vb], Vs[vb + 4 * APAD]);
            }
        }
    }

    // epilogue: normalize and store
    const float inv0 = 1.f / l0;
    const float inv1 = 1.f / l1;
    const size_t row0 = (size_t)(b * SS + pos0) * QDIM + h * HDD;
    const size_t row1 = (size_t)(b * SS + pos1) * QDIM + h * HDD;
    #pragma unroll
    for (int nt = 0; nt < 8; nt++) {
        const int col = nt * 8 + 2 * gx;
        *(float2*)&g_y[row0 + col] = make_float2(Oa[nt][0] * inv0, Oa[nt][1] * inv0);
        *(float2*)&g_y[row1 + col] = make_float2(Oa[nt][2] * inv1, Oa[nt][3] * inv1);
    }
}

// ---------------------------------------------------------------------------
// Launch: qkv GEMM -> rope/rms/gate -> flash attention -> proj GEMM
// Inputs: 0 x, 1 ve, 2 cos, 3 sin, 4 attn_mask(unused), 5 Wq, 6 Wk, 7 Wv,
//         8 Wproj, 9 Wgate. Output: float32 (B,S,E).
// ---------------------------------------------------------------------------
extern "C" void kernel_launch(void* const* d_in, const int* in_sizes, int n_in,
                              void* d_out, int out_size)
{
    const float* x     = (const float*)d_in[0];
    const float* ve    = (const float*)d_in[1];
    const float* cosb  = (const float*)d_in[2];
    const float* sinb  = (const float*)d_in[3];
    const float* Wq    = (const float*)d_in[5];
    const float* Wk    = (const float*)d_in[6];
    const float* Wv    = (const float*)d_in[7];
    const float* Wproj = (const float*)d_in[8];
    const float* Wgate = (const float*)d_in[9];
    float* out = (float*)d_out;

    (void)in_sizes; (void)n_in; (void)out_size;

    cudaFuncSetAttribute(attn_kernel,
                         cudaFuncAttributeMaxDynamicSharedMemorySize,
                         ATTN_SMEM_BYTES);

    // 1) QKV projection: grid (1536/128, 4096/128)
    gemm_qkv<<<dim3(12, 32), 256>>>(x, Wq, Wk, Wv);

    // 2) RoPE + RMS + gated-ve
    rope_gate<<<(MM * 24) / 4, 128>>>(x, ve, cosb, sinb, Wgate);

    // 3) Flash attention (GQA-shared): (pos-tiles of 32, kv heads, batch)
    attn_kernel<<<dim3(SS / 32, NKVV, BB), 256, ATTN_SMEM_BYTES>>>();

    // 4) Output projection: grid (1024/128, 4096/128)
    gemm_proj<<<dim3(8, 32), 256>>>(Wproj, out);
}

// round 15
// speedup vs baseline: 1.2742x; 1.1633x over previous
#include <cuda_runtime.h>
#include <math.h>
#include <stdint.h>

// Problem constants
#define BB   2
#define SS   2048
#define EE   1024
#define NHH  16
#define NKVV 4
#define HDD  64
#define GCH  12
#define MM   (BB * SS)        // 4096 tokens
#define QDIM (NHH * HDD)      // 1024
#define KVDIM (NKVV * HDD)    // 256

// Scratch (device globals: allocation-free rule)
__device__ float g_q[MM * QDIM];    // 16 MB
__device__ float g_k[MM * KVDIM];   //  4 MB
__device__ float g_v[MM * KVDIM];   //  4 MB
__device__ float g_y[MM * QDIM];    // 16 MB

// ---------------------------------------------------------------------------
// tf32 helpers
// ---------------------------------------------------------------------------
__device__ __forceinline__ unsigned f2tf(float x) {
    unsigned u;
    asm("cvt.rna.tf32.f32 %0, %1;" : "=r"(u) : "f"(x));
    return u;
}

// D += A(16x8) * B(8x8), tf32 inputs, f32 accumulate
__device__ __forceinline__ void mma8(float* c,
                                     unsigned a0, unsigned a1, unsigned a2, unsigned a3,
                                     unsigned b0, unsigned b1) {
    asm volatile(
        "mma.sync.aligned.m16n8k8.row.col.f32.tf32.tf32.f32 "
        "{%0,%1,%2,%3},{%4,%5,%6,%7},{%8,%9},{%0,%1,%2,%3};"
        : "+f"(c[0]), "+f"(c[1]), "+f"(c[2]), "+f"(c[3])
        : "r"(a0), "r"(a1), "r"(a2), "r"(a3), "r"(b0), "r"(b1));
}

__device__ __forceinline__ float* qkv_ptr(int row, int col) {
    if (col < QDIM)         return &g_q[(size_t)row * QDIM + col];
    if (col < QDIM + KVDIM) return &g_k[(size_t)row * KVDIM + (col - QDIM)];
    return &g_v[(size_t)row * KVDIM + (col - QDIM - KVDIM)];
}

// ---------------------------------------------------------------------------
// GEMM 1: [q|k|v] = X (4096x1024) @ [Wq;Wk;Wv]^T (1536x1024), tf32 mma
// 128x128 block, k-chunk 32, 8 warps (2x4), warp tile 64x32, reg prefetch.
// Round-5 proven layout: GPAD 36, scalar LDS fragments (interleaved LDS.64
// variant measured SLOWER in rounds 8/13). launch_bounds(256,2) pins the
// 2-block/SM residency round 5 achieved at 128 regs.
// ---------------------------------------------------------------------------
#define GPAD 36

__global__ void __launch_bounds__(256, 2) gemm_qkv(
    const float* __restrict__ X,
    const float* __restrict__ Wq,
    const float* __restrict__ Wk,
    const float* __restrict__ Wv)
{
    __shared__ unsigned As[128 * GPAD];
    __shared__ unsigned Bs[128 * GPAD];

    const int bm = blockIdx.y * 128;
    const int bn = blockIdx.x * 128;
    const int tid = threadIdx.x;
    const int lane = tid & 31;
    const int wid = tid >> 5;
    const int wm = (wid >> 2) * 64;   // 0 or 64
    const int wn = (wid & 3) * 32;    // 0..96
    const int gy = lane >> 2;         // 0..7
    const int gx = lane & 3;          // 0..3

    const int srow = tid >> 3;          // base row 0..31 (stride 32 via p)
    const int sc4  = (tid & 7) * 4;     // col 0,4,..,28

    const float* aptr = X + (size_t)(bm + srow) * EE + sc4;
    const float* bptr[4];
    #pragma unroll
    for (int p = 0; p < 4; p++) {
        const int n = bn + srow + 32 * p;
        if (n < QDIM)                bptr[p] = Wq + (size_t)n * EE + sc4;
        else if (n < QDIM + KVDIM)   bptr[p] = Wk + (size_t)(n - QDIM) * EE + sc4;
        else                         bptr[p] = Wv + (size_t)(n - QDIM - KVDIM) * EE + sc4;
    }

    float acc[4][4][4];
    #pragma unroll
    for (int mt = 0; mt < 4; mt++)
        #pragma unroll
        for (int nt = 0; nt < 4; nt++)
            #pragma unroll
            for (int e = 0; e < 4; e++) acc[mt][nt][e] = 0.f;

    float4 ra[4], rb[4];
    #pragma unroll
    for (int p = 0; p < 4; p++) {
        ra[p] = *(const float4*)(aptr + (size_t)(32 * p) * EE);
        rb[p] = *(const float4*)(bptr[p]);
    }

    for (int k0 = 0; k0 < EE; k0 += 32) {
        __syncthreads();
        #pragma unroll
        for (int p = 0; p < 4; p++) {
            const int r = srow + 32 * p;
            unsigned* a = &As[r * GPAD + sc4];
            a[0] = f2tf(ra[p].x); a[1] = f2tf(ra[p].y);
            a[2] = f2tf(ra[p].z); a[3] = f2tf(ra[p].w);
            unsigned* b = &Bs[r * GPAD + sc4];
            b[0] = f2tf(rb[p].x); b[1] = f2tf(rb[p].y);
            b[2] = f2tf(rb[p].z); b[3] = f2tf(rb[p].w);
        }
        __syncthreads();
        if (k0 + 32 < EE) {
            #pragma unroll
            for (int p = 0; p < 4; p++) {
                ra[p] = *(const float4*)(aptr + (size_t)(32 * p) * EE + k0 + 32);
                rb[p] = *(const float4*)(bptr[p] + k0 + 32);
            }
        }
        #pragma unroll
        for (int ks = 0; ks < 4; ks++) {
            unsigned af[4][4], bf[4][2];
            #pragma unroll
            for (int mt = 0; mt < 4; mt++) {
                const int base = (wm + mt * 16 + gy) * GPAD + ks * 8 + gx;
                af[mt][0] = As[base];
                af[mt][1] = As[base + 8 * GPAD];
                af[mt][2] = As[base + 4];
                af[mt][3] = As[base + 8 * GPAD + 4];
            }
            #pragma unroll
            for (int nt = 0; nt < 4; nt++) {
                const int base = (wn + nt * 8 + gy) * GPAD + ks * 8 + gx;
                bf[nt][0] = Bs[base];
                bf[nt][1] = Bs[base + 4];
            }
            #pragma unroll
            for (int mt = 0; mt < 4; mt++)
                #pragma unroll
                for (int nt = 0; nt < 4; nt++)
                    mma8(acc[mt][nt], af[mt][0], af[mt][1], af[mt][2], af[mt][3],
                         bf[nt][0], bf[nt][1]);
        }
    }

    #pragma unroll
    for (int mt = 0; mt < 4; mt++) {
        #pragma unroll
        for (int nt = 0; nt < 4; nt++) {
            const int row = bm + wm + mt * 16 + gy;
            const int col = bn + wn + nt * 8 + 2 * gx;
            *(float2*)qkv_ptr(row, col)     = make_float2(acc[mt][nt][0], acc[mt][nt][1]);
            *(float2*)qkv_ptr(row + 8, col) = make_float2(acc[mt][nt][2], acc[mt][nt][3]);
        }
    }
}

// ---------------------------------------------------------------------------
// GEMM 2: out = y (4096x1024) @ Wproj^T (1024x1024), tf32 mma (round-5 layout)
// ---------------------------------------------------------------------------
__global__ void __launch_bounds__(256, 2) gemm_proj(
    const float* __restrict__ W, float* __restrict__ C)
{
    __shared__ unsigned As[128 * GPAD];
    __shared__ unsigned Bs[128 * GPAD];

    const int bm = blockIdx.y * 128;
    const int bn = blockIdx.x * 128;
    const int tid = threadIdx.x;
    const int lane = tid & 31;
    const int wid = tid >> 5;
    const int wm = (wid >> 2) * 64;
    const int wn = (wid & 3) * 32;
    const int gy = lane >> 2;
    const int gx = lane & 3;

    const int srow = tid >> 3;
    const int sc4  = (tid & 7) * 4;

    const float* aptr = g_y + (size_t)(bm + srow) * EE + sc4;
    const float* bptr = W + (size_t)(bn + srow) * EE + sc4;

    float acc[4][4][4];
    #pragma unroll
    for (int mt = 0; mt < 4; mt++)
        #pragma unroll
        for (int nt = 0; nt < 4; nt++)
            #pragma unroll
            for (int e = 0; e < 4; e++) acc[mt][nt][e] = 0.f;

    float4 ra[4], rb[4];
    #pragma unroll
    for (int p = 0; p < 4; p++) {
        ra[p] = *(const float4*)(aptr + (size_t)(32 * p) * EE);
        rb[p] = *(const float4*)(bptr + (size_t)(32 * p) * EE);
    }

    for (int k0 = 0; k0 < EE; k0 += 32) {
        __syncthreads();
        #pragma unroll
        for (int p = 0; p < 4; p++) {
            const int r = srow + 32 * p;
            unsigned* a = &As[r * GPAD + sc4];
            a[0] = f2tf(ra[p].x); a[1] = f2tf(ra[p].y);
            a[2] = f2tf(ra[p].z); a[3] = f2tf(ra[p].w);
            unsigned* b = &Bs[r * GPAD + sc4];
            b[0] = f2tf(rb[p].x); b[1] = f2tf(rb[p].y);
            b[2] = f2tf(rb[p].z); b[3] = f2tf(rb[p].w);
        }
        __syncthreads();
        if (k0 + 32 < EE) {
            #pragma unroll
            for (int p = 0; p < 4; p++) {
                ra[p] = *(const float4*)(aptr + (size_t)(32 * p) * EE + k0 + 32);
                rb[p] = *(const float4*)(bptr + (size_t)(32 * p) * EE + k0 + 32);
            }
        }
        #pragma unroll
        for (int ks = 0; ks < 4; ks++) {
            unsigned af[4][4], bf[4][2];
            #pragma unroll
            for (int mt = 0; mt < 4; mt++) {
                const int base = (wm + mt * 16 + gy) * GPAD + ks * 8 + gx;
                af[mt][0] = As[base];
                af[mt][1] = As[base + 8 * GPAD];
                af[mt][2] = As[base + 4];
                af[mt][3] = As[base + 8 * GPAD + 4];
            }
            #pragma unroll
            for (int nt = 0; nt < 4; nt++) {
                const int base = (wn + nt * 8 + gy) * GPAD + ks * 8 + gx;
                bf[nt][0] = Bs[base];
                bf[nt][1] = Bs[base + 4];
            }
            #pragma unroll
            for (int mt = 0; mt < 4; mt++)
                #pragma unroll
                for (int nt = 0; nt < 4; nt++)
                    mma8(acc[mt][nt], af[mt][0], af[mt][1], af[mt][2], af[mt][3],
                         bf[nt][0], bf[nt][1]);
        }
    }

    #pragma unroll
    for (int mt = 0; mt < 4; mt++) {
        #pragma unroll
        for (int nt = 0; nt < 4; nt++) {
            const int row = bm + wm + mt * 16 + gy;
            const int col = bn + wn + nt * 8 + 2 * gx;
            *(float2*)&C[(size_t)row * EE + col] =
                make_float2(acc[mt][nt][0], acc[mt][nt][1]);
            *(float2*)&C[(size_t)(row + 8) * EE + col] =
                make_float2(acc[mt][nt][2], acc[mt][nt][3]);
        }
    }
}

// ---------------------------------------------------------------------------
// Epilogue: RoPE + RMS-norm on q (16 heads) and k (4 heads); gated ve add
// on v (4 heads). One warp per (token, unit), unit in [0,24). (unchanged)
// ---------------------------------------------------------------------------
__global__ void __launch_bounds__(128) rope_gate(
    const float* __restrict__ X, const float* __restrict__ VE,
    const float* __restrict__ Cos, const float* __restrict__ Sin,
    const float* __restrict__ Wgate)
{
    const int gw = blockIdx.x * 4 + (threadIdx.x >> 5);
    const int lane = threadIdx.x & 31;
    const int token = gw / 24;
    const int unit = gw - token * 24;
    const int s = token & (SS - 1);

    if (unit >= 20) {  // v gate
        const int kv = unit - 20;
        const float* xr = X + (size_t)token * EE;
        float g = 0.f;
        #pragma unroll
        for (int c = 0; c < GCH; c++) g = fmaf(xr[c], Wgate[kv * GCH + c], g);
        g = 3.f / (1.f + __expf(-g));
        float* vb = g_v + (size_t)token * KVDIM + kv * HDD;
        const float* veb = VE + (size_t)token * KVDIM + kv * HDD;
        vb[lane]      += g * veb[lane];
        vb[lane + 32] += g * veb[lane + 32];
        return;
    }

    float* base = (unit < NHH)
        ? g_q + (size_t)token * QDIM + unit * HDD
        : g_k + (size_t)token * KVDIM + (unit - NHH) * HDD;

    const float c  = Cos[s * 32 + lane];
    const float sn = Sin[s * 32 + lane];
    const float x1 = base[lane];
    const float x2 = base[lane + 32];
    const float o1 =  x1 * c + x2 * sn;
    const float o2 = -x1 * sn + x2 * c;
    float ssum = o1 * o1 + o2 * o2;
    #pragma unroll
    for (int off = 16; off; off >>= 1)
        ssum += __shfl_xor_sync(0xffffffffu, ssum, off);
    const float inv = rsqrtf(ssum * (1.f / 64.f) + 1.1920928955078125e-07f) * 1.2f;
    base[lane]      = o1 * inv;
    base[lane + 32] = o2 * inv;
}

// ---------------------------------------------------------------------------
// Flash attention, GQA-shared (round-13, confirmed win): one block = one
// kv-head x 32 q-positions x all 4 q-heads = 128 virtual q-rows. 8 warps,
// 16-row bands. KV tiles of 64 positions, register-prefetch double buffered.
// Interleaved smem layout -> LDS.64 fragments. Q buffer reused for P.
// smem: Qs 128x72 | Ks 64x72 | Vs 64x72 = 73728 B (dynamic)
// ---------------------------------------------------------------------------
#define APAD 72
#define ATTN_SMEM_BYTES (256 * APAD * 4)

__global__ void __launch_bounds__(256) attn_kernel()
{
    extern __shared__ unsigned sm[];
    unsigned* Qs = sm;                  // reused as P after frag extraction
    unsigned* Ks = sm + 128 * APAD;
    unsigned* Vs = sm + 192 * APAD;

    const int qp  = blockIdx.x;         // q position tile of 32 (64)
    const int hkv = blockIdx.y;         // kv head (4)
    const int b   = blockIdx.z;         // batch (2)
    const int q0  = qp * 32;
    const int tid = threadIdx.x;
    const int lane = tid & 31;
    const int wid = tid >> 5;           // 0..7
    const int gy = lane >> 2;
    const int gx = lane & 3;
    const int r0 = wid * 16 + gy;       // virtual row (head*32 + pos offset)
    const int h  = hkv * 4 + (wid >> 1);
    const int pos0 = q0 + ((wid & 1) * 16 + gy);
    const int pos1 = pos0 + 8;

    // Stage Q (scaled by 1/8), interleaved tf32
    for (int idx = tid; idx < 128 * 16; idx += 256) {
        const int r = idx >> 4, c4 = (idx & 15) * 4;
        const float4 v = *(const float4*)&g_q[(size_t)(b * SS + q0 + (r & 31)) * QDIM
                                              + (hkv * 4 + (r >> 5)) * HDD + c4];
        unsigned* q = &Qs[r * APAD + (c4 & ~7) + ((c4 >> 2) & 1)];
        q[0] = f2tf(v.x * 0.125f); q[2] = f2tf(v.y * 0.125f);
        q[4] = f2tf(v.z * 0.125f); q[6] = f2tf(v.w * 0.125f);
    }
    __syncthreads();

    // Extract Q fragments (reused across all kv tiles)
    unsigned qa[8][4];
    #pragma unroll
    for (int ks = 0; ks < 8; ks++) {
        const uint2 lo = *(const uint2*)&Qs[r0 * APAD + ks * 8 + 2 * gx];
        const uint2 hi = *(const uint2*)&Qs[(r0 + 8) * APAD + ks * 8 + 2 * gx];
        qa[ks][0] = lo.x; qa[ks][1] = hi.x; qa[ks][2] = lo.y; qa[ks][3] = hi.y;
    }

    float Oa[8][4];
    #pragma unroll
    for (int nt = 0; nt < 8; nt++)
        #pragma unroll
        for (int e = 0; e < 4; e++) Oa[nt][e] = 0.f;
    float m0 = -1e30f, m1 = -1e30f, l0 = 0.f, l1 = 0.f;

    const int ntiles = (q0 + 95) >> 6;
    const int c4s  = (tid & 15) * 4;
    const int rb   = tid >> 4;                         // 0..15
    const int soff = (c4s & ~7) + ((c4s >> 2) & 1);
    const int pg   = (gy & 3) * 2 + (gy >> 2);         // interleaved col of gy
    const int pc0  = ((2 * gx) & 3) * 2 + (((2 * gx) >> 2) & 1);
    const int pc1  = ((2 * gx + 1) & 3) * 2 + (((2 * gx + 1) >> 2) & 1);
    const float* kp = g_k + (size_t)(b * SS) * KVDIM + hkv * HDD + c4s;
    const float* vp = g_v + (size_t)(b * SS) * KVDIM + hkv * HDD + c4s;

    float4 rk[4], rv[4];
    #pragma unroll
    for (int c = 0; c < 4; c++) {
        const size_t ro = (size_t)(rb + 16 * c) * KVDIM;
        rk[c] = *(const float4*)(kp + ro);
        rv[c] = *(const float4*)(vp + ro);
    }

    for (int j = 0; j < ntiles; j++) {
        __syncthreads();   // prior tile's consumers (incl. P in Qs) done
        #pragma unroll
        for (int c = 0; c < 4; c++) {
            unsigned* kd = &Ks[(rb + 16 * c) * APAD + soff];
            kd[0] = f2tf(rk[c].x); kd[2] = f2tf(rk[c].y);
            kd[4] = f2tf(rk[c].z); kd[6] = f2tf(rk[c].w);
            unsigned* vd = &Vs[(rb + 16 * c) * APAD + soff];
            vd[0] = f2tf(rv[c].x); vd[2] = f2tf(rv[c].y);
            vd[4] = f2tf(rv[c].z); vd[6] = f2tf(rv[c].w);
        }
        __syncthreads();
        if (j + 1 < ntiles) {  // prefetch next tile (latency hidden by mmas)
            const size_t tb = (size_t)((j + 1) * 64) * KVDIM;
            #pragma unroll
            for (int c = 0; c < 4; c++) {
                const size_t ro = tb + (size_t)(rb + 16 * c) * KVDIM;
                rk[c] = *(const float4*)(kp + ro);
                rv[c] = *(const float4*)(vp + ro);
            }
        }

        // S = Q K^T
        float sf[8][4];
        #pragma unroll
        for (int nt = 0; nt < 8; nt++)
            #pragma unroll
            for (int e = 0; e < 4; e++) sf[nt][e] = 0.f;
        #pragma unroll
        for (int ks = 0; ks < 8; ks++) {
            #pragma unroll
            for (int nt = 0; nt < 8; nt++) {
                const uint2 kb = *(const uint2*)&Ks[(nt * 8 + gy) * APAD + ks * 8 + 2 * gx];
                mma8(sf[nt], qa[ks][0], qa[ks][1], qa[ks][2], qa[ks][3], kb.x, kb.y);
            }
        }

        // causal mask (last tile only); scale folded into Q
        if (j == ntiles - 1) {
            #pragma unroll
            for (int nt = 0; nt < 8; nt++) {
                const int c = j * 64 + nt * 8 + 2 * gx;
                if (c     > pos0) sf[nt][0] = -1e30f;
                if (c + 1 > pos0) sf[nt][1] = -1e30f;
                if (c     > pos1) sf[nt][2] = -1e30f;
                if (c + 1 > pos1) sf[nt][3] = -1e30f;
            }
        }

        // online softmax (rows pos0: elems 0,1 / pos1: elems 2,3)
        float mx0 = -1e30f, mx1 = -1e30f;
        #pragma unroll
        for (int nt = 0; nt < 8; nt++) {
            mx0 = fmaxf(mx0, fmaxf(sf[nt][0], sf[nt][1]));
            mx1 = fmaxf(mx1, fmaxf(sf[nt][2], sf[nt][3]));
        }
        mx0 = fmaxf(mx0, __shfl_xor_sync(0xffffffffu, mx0, 1));
        mx0 = fmaxf(mx0, __shfl_xor_sync(0xffffffffu, mx0, 2));
        mx1 = fmaxf(mx1, __shfl_xor_sync(0xffffffffu, mx1, 1));
        mx1 = fmaxf(mx1, __shfl_xor_sync(0xffffffffu, mx1, 2));
        const float mn0 = fmaxf(m0, mx0);
        const float mn1 = fmaxf(m1, mx1);
        float ps0 = 0.f, ps1 = 0.f;
        #pragma unroll
        for (int nt = 0; nt < 8; nt++) {
            sf[nt][0] = __expf(sf[nt][0] - mn0);
            sf[nt][1] = __expf(sf[nt][1] - mn0);
            sf[nt][2] = __expf(sf[nt][2] - mn1);
            sf[nt][3] = __expf(sf[nt][3] - mn1);
            ps0 += sf[nt][0] + sf[nt][1];
            ps1 += sf[nt][2] + sf[nt][3];
        }
        ps0 += __shfl_xor_sync(0xffffffffu, ps0, 1);
        ps0 += __shfl_xor_sync(0xffffffffu, ps0, 2);
        ps1 += __shfl_xor_sync(0xffffffffu, ps1, 1);
        ps1 += __shfl_xor_sync(0xffffffffu, ps1, 2);
        const float scl0 = __expf(m0 - mn0);
        const float scl1 = __expf(m1 - mn1);
        l0 = l0 * scl0 + ps0;
        l1 = l1 * scl1 + ps1;
        m0 = mn0; m1 = mn1;

        // store P (interleaved) into Q buffer: warp-private 16-row band
        #pragma unroll
        for (int nt = 0; nt < 8; nt++) {
            const int a = r0 * APAD + nt * 8;
            Qs[a + pc0] = f2tf(sf[nt][0]);
            Qs[a + pc1] = f2tf(sf[nt][1]);
            Qs[a + 8 * APAD + pc0] = f2tf(sf[nt][2]);
            Qs[a + 8 * APAD + pc1] = f2tf(sf[nt][3]);
        }
        __syncwarp();

        // rescale O
        #pragma unroll
        for (int nt = 0; nt < 8; nt++) {
            Oa[nt][0] *= scl0; Oa[nt][1] *= scl0;
            Oa[nt][2] *= scl1; Oa[nt][3] *= scl1;
        }

        // O += P V
        #pragma unroll
        for (int ks = 0; ks < 8; ks++) {
            const uint2 plo = *(const uint2*)&Qs[r0 * APAD + ks * 8 + 2 * gx];
            const uint2 phi = *(const uint2*)&Qs[(r0 + 8) * APAD + ks * 8 + 2 * gx];
            #pragma unroll
            for (int nt = 0; nt < 8; nt++) {
                const int vb = (ks * 8 + gx) * APAD + nt * 8 + pg;
                mma8(Oa[nt], plo.x, phi.x, plo.y, phi.y, Vs[vb], Vs[vb + 4 * APAD]);
            }
        }
    }

    // epilogue: normalize and store
    const float inv0 = 1.f / l0;
    const float inv1 = 1.f / l1;
    const size_t row0 = (size_t)(b * SS + pos0) * QDIM + h * HDD;
    const size_t row1 = (size_t)(b * SS + pos1) * QDIM + h * HDD;
    #pragma unroll
    for (int nt = 0; nt < 8; nt++) {
        const int col = nt * 8 + 2 * gx;
        *(float2*)&g_y[row0 + col] = make_float2(Oa[nt][0] * inv0, Oa[nt][1] * inv0);
        *(float2*)&g_y[row1 + col] = make_float2(Oa[nt][2] * inv1, Oa[nt][3] * inv1);
    }
}

// ---------------------------------------------------------------------------
// Launch: qkv GEMM -> rope/rms/gate -> flash attention -> proj GEMM
// Inputs: 0 x, 1 ve, 2 cos, 3 sin, 4 attn_mask(unused), 5 Wq, 6 Wk, 7 Wv,
//         8 Wproj, 9 Wgate. Output: float32 (B,S,E).
// ---------------------------------------------------------------------------
extern "C" void kernel_launch(void* const* d_in, const int* in_sizes, int n_in,
                              void* d_out, int out_size)
{
    const float* x     = (const float*)d_in[0];
    const float* ve    = (const float*)d_in[1];
    const float* cosb  = (const float*)d_in[2];
    const float* sinb  = (const float*)d_in[3];
    const float* Wq    = (const float*)d_in[5];
    const float* Wk    = (const float*)d_in[6];
    const float* Wv    = (const float*)d_in[7];
    const float* Wproj = (const float*)d_in[8];
    const float* Wgate = (const float*)d_in[9];
    float* out = (float*)d_out;

    (void)in_sizes; (void)n_in; (void)out_size;

    cudaFuncSetAttribute(attn_kernel,
                         cudaFuncAttributeMaxDynamicSharedMemorySize,
                         ATTN_SMEM_BYTES);

    // 1) QKV projection: grid (1536/128, 4096/128)
    gemm_qkv<<<dim3(12, 32), 256>>>(x, Wq, Wk, Wv);

    // 2) RoPE + RMS + gated-ve
    rope_gate<<<(MM * 24) / 4, 128>>>(x, ve, cosb, sinb, Wgate);

    // 3) Flash attention (GQA-shared): (pos-tiles of 32, kv heads, batch)
    attn_kernel<<<dim3(SS / 32, NKVV, BB), 256, ATTN_SMEM_BYTES>>>();

    // 4) Output projection: grid (1024/128, 4096/128)
    gemm_proj<<<dim3(8, 32), 256>>>(Wproj, out);
}

// round 17
// speedup vs baseline: 1.3181x; 1.0345x over previous
#include <cuda_runtime.h>
#include <math.h>
#include <stdint.h>

// Problem constants
#define BB   2
#define SS   2048
#define EE   1024
#define NHH  16
#define NKVV 4
#define HDD  64
#define GCH  12
#define MM   (BB * SS)        // 4096 tokens
#define QDIM (NHH * HDD)      // 1024
#define KVDIM (NKVV * HDD)    // 256

// Scratch (device globals: allocation-free rule)
__device__ float g_q[MM * QDIM];    // 16 MB
__device__ float g_k[MM * KVDIM];   //  4 MB
__device__ float g_v[MM * KVDIM];   //  4 MB
__device__ float g_y[MM * QDIM];    // 16 MB

// ---------------------------------------------------------------------------
// tf32 helpers
// ---------------------------------------------------------------------------
__device__ __forceinline__ unsigned f2tf(float x) {
    unsigned u;
    asm("cvt.rna.tf32.f32 %0, %1;" : "=r"(u) : "f"(x));
    return u;
}

// D += A(16x8) * B(8x8), tf32 inputs, f32 accumulate
__device__ __forceinline__ void mma8(float* c,
                                     unsigned a0, unsigned a1, unsigned a2, unsigned a3,
                                     unsigned b0, unsigned b1) {
    asm volatile(
        "mma.sync.aligned.m16n8k8.row.col.f32.tf32.tf32.f32 "
        "{%0,%1,%2,%3},{%4,%5,%6,%7},{%8,%9},{%0,%1,%2,%3};"
        : "+f"(c[0]), "+f"(c[1]), "+f"(c[2]), "+f"(c[3])
        : "r"(a0), "r"(a1), "r"(a2), "r"(a3), "r"(b0), "r"(b1));
}

__device__ __forceinline__ float* qkv_ptr(int row, int col) {
    if (col < QDIM)         return &g_q[(size_t)row * QDIM + col];
    if (col < QDIM + KVDIM) return &g_k[(size_t)row * KVDIM + (col - QDIM)];
    return &g_v[(size_t)row * KVDIM + (col - QDIM - KVDIM)];
}

// ---------------------------------------------------------------------------
// GEMM 1: [q|k|v] = X (4096x1024) @ [Wq;Wk;Wv]^T (1536x1024), tf32 mma
// 128x128 block, k-chunk 32, 8 warps (2x4), warp tile 64x32, reg prefetch.
// Round-5 proven layout: GPAD 36, scalar LDS fragments. (UNCHANGED)
// ---------------------------------------------------------------------------
#define GPAD 36

__global__ void __launch_bounds__(256, 2) gemm_qkv(
    const float* __restrict__ X,
    const float* __restrict__ Wq,
    const float* __restrict__ Wk,
    const float* __restrict__ Wv)
{
    __shared__ unsigned As[128 * GPAD];
    __shared__ unsigned Bs[128 * GPAD];

    const int bm = blockIdx.y * 128;
    const int bn = blockIdx.x * 128;
    const int tid = threadIdx.x;
    const int lane = tid & 31;
    const int wid = tid >> 5;
    const int wm = (wid >> 2) * 64;   // 0 or 64
    const int wn = (wid & 3) * 32;    // 0..96
    const int gy = lane >> 2;         // 0..7
    const int gx = lane & 3;          // 0..3

    const int srow = tid >> 3;          // base row 0..31 (stride 32 via p)
    const int sc4  = (tid & 7) * 4;     // col 0,4,..,28

    const float* aptr = X + (size_t)(bm + srow) * EE + sc4;
    const float* bptr[4];
    #pragma unroll
    for (int p = 0; p < 4; p++) {
        const int n = bn + srow + 32 * p;
        if (n < QDIM)                bptr[p] = Wq + (size_t)n * EE + sc4;
        else if (n < QDIM + KVDIM)   bptr[p] = Wk + (size_t)(n - QDIM) * EE + sc4;
        else                         bptr[p] = Wv + (size_t)(n - QDIM - KVDIM) * EE + sc4;
    }

    float acc[4][4][4];
    #pragma unroll
    for (int mt = 0; mt < 4; mt++)
        #pragma unroll
        for (int nt = 0; nt < 4; nt++)
            #pragma unroll
            for (int e = 0; e < 4; e++) acc[mt][nt][e] = 0.f;

    float4 ra[4], rb[4];
    #pragma unroll
    for (int p = 0; p < 4; p++) {
        ra[p] = *(const float4*)(aptr + (size_t)(32 * p) * EE);
        rb[p] = *(const float4*)(bptr[p]);
    }

    for (int k0 = 0; k0 < EE; k0 += 32) {
        __syncthreads();
        #pragma unroll
        for (int p = 0; p < 4; p++) {
            const int r = srow + 32 * p;
            unsigned* a = &As[r * GPAD + sc4];
            a[0] = f2tf(ra[p].x); a[1] = f2tf(ra[p].y);
            a[2] = f2tf(ra[p].z); a[3] = f2tf(ra[p].w);
            unsigned* b = &Bs[r * GPAD + sc4];
            b[0] = f2tf(rb[p].x); b[1] = f2tf(rb[p].y);
            b[2] = f2tf(rb[p].z); b[3] = f2tf(rb[p].w);
        }
        __syncthreads();
        if (k0 + 32 < EE) {
            #pragma unroll
            for (int p = 0; p < 4; p++) {
                ra[p] = *(const float4*)(aptr + (size_t)(32 * p) * EE + k0 + 32);
                rb[p] = *(const float4*)(bptr[p] + k0 + 32);
            }
        }
        #pragma unroll
        for (int ks = 0; ks < 4; ks++) {
            unsigned af[4][4], bf[4][2];
            #pragma unroll
            for (int mt = 0; mt < 4; mt++) {
                const int base = (wm + mt * 16 + gy) * GPAD + ks * 8 + gx;
                af[mt][0] = As[base];
                af[mt][1] = As[base + 8 * GPAD];
                af[mt][2] = As[base + 4];
                af[mt][3] = As[base + 8 * GPAD + 4];
            }
            #pragma unroll
            for (int nt = 0; nt < 4; nt++) {
                const int base = (wn + nt * 8 + gy) * GPAD + ks * 8 + gx;
                bf[nt][0] = Bs[base];
                bf[nt][1] = Bs[base + 4];
            }
            #pragma unroll
            for (int mt = 0; mt < 4; mt++)
                #pragma unroll
                for (int nt = 0; nt < 4; nt++)
                    mma8(acc[mt][nt], af[mt][0], af[mt][1], af[mt][2], af[mt][3],
                         bf[nt][0], bf[nt][1]);
        }
    }

    #pragma unroll
    for (int mt = 0; mt < 4; mt++) {
        #pragma unroll
        for (int nt = 0; nt < 4; nt++) {
            const int row = bm + wm + mt * 16 + gy;
            const int col = bn + wn + nt * 8 + 2 * gx;
            *(float2*)qkv_ptr(row, col)     = make_float2(acc[mt][nt][0], acc[mt][nt][1]);
            *(float2*)qkv_ptr(row + 8, col) = make_float2(acc[mt][nt][2], acc[mt][nt][3]);
        }
    }
}

// ---------------------------------------------------------------------------
// GEMM 2: out = y (4096x1024) @ Wproj^T (1024x1024), tf32 mma (UNCHANGED)
// ---------------------------------------------------------------------------
__global__ void __launch_bounds__(256, 2) gemm_proj(
    const float* __restrict__ W, float* __restrict__ C)
{
    __shared__ unsigned As[128 * GPAD];
    __shared__ unsigned Bs[128 * GPAD];

    const int bm = blockIdx.y * 128;
    const int bn = blockIdx.x * 128;
    const int tid = threadIdx.x;
    const int lane = tid & 31;
    const int wid = tid >> 5;
    const int wm = (wid >> 2) * 64;
    const int wn = (wid & 3) * 32;
    const int gy = lane >> 2;
    const int gx = lane & 3;

    const int srow = tid >> 3;
    const int sc4  = (tid & 7) * 4;

    const float* aptr = g_y + (size_t)(bm + srow) * EE + sc4;
    const float* bptr = W + (size_t)(bn + srow) * EE + sc4;

    float acc[4][4][4];
    #pragma unroll
    for (int mt = 0; mt < 4; mt++)
        #pragma unroll
        for (int nt = 0; nt < 4; nt++)
            #pragma unroll
            for (int e = 0; e < 4; e++) acc[mt][nt][e] = 0.f;

    float4 ra[4], rb[4];
    #pragma unroll
    for (int p = 0; p < 4; p++) {
        ra[p] = *(const float4*)(aptr + (size_t)(32 * p) * EE);
        rb[p] = *(const float4*)(bptr + (size_t)(32 * p) * EE);
    }

    for (int k0 = 0; k0 < EE; k0 += 32) {
        __syncthreads();
        #pragma unroll
        for (int p = 0; p < 4; p++) {
            const int r = srow + 32 * p;
            unsigned* a = &As[r * GPAD + sc4];
            a[0] = f2tf(ra[p].x); a[1] = f2tf(ra[p].y);
            a[2] = f2tf(ra[p].z); a[3] = f2tf(ra[p].w);
            unsigned* b = &Bs[r * GPAD + sc4];
            b[0] = f2tf(rb[p].x); b[1] = f2tf(rb[p].y);
            b[2] = f2tf(rb[p].z); b[3] = f2tf(rb[p].w);
        }
        __syncthreads();
        if (k0 + 32 < EE) {
            #pragma unroll
            for (int p = 0; p < 4; p++) {
                ra[p] = *(const float4*)(aptr + (size_t)(32 * p) * EE + k0 + 32);
                rb[p] = *(const float4*)(bptr + (size_t)(32 * p) * EE + k0 + 32);
            }
        }
        #pragma unroll
        for (int ks = 0; ks < 4; ks++) {
            unsigned af[4][4], bf[4][2];
            #pragma unroll
            for (int mt = 0; mt < 4; mt++) {
                const int base = (wm + mt * 16 + gy) * GPAD + ks * 8 + gx;
                af[mt][0] = As[base];
                af[mt][1] = As[base + 8 * GPAD];
                af[mt][2] = As[base + 4];
                af[mt][3] = As[base + 8 * GPAD + 4];
            }
            #pragma unroll
            for (int nt = 0; nt < 4; nt++) {
                const int base = (wn + nt * 8 + gy) * GPAD + ks * 8 + gx;
                bf[nt][0] = Bs[base];
                bf[nt][1] = Bs[base + 4];
            }
            #pragma unroll
            for (int mt = 0; mt < 4; mt++)
                #pragma unroll
                for (int nt = 0; nt < 4; nt++)
                    mma8(acc[mt][nt], af[mt][0], af[mt][1], af[mt][2], af[mt][3],
                         bf[nt][0], bf[nt][1]);
        }
    }

    #pragma unroll
    for (int mt = 0; mt < 4; mt++) {
        #pragma unroll
        for (int nt = 0; nt < 4; nt++) {
            const int row = bm + wm + mt * 16 + gy;
            const int col = bn + wn + nt * 8 + 2 * gx;
            *(float2*)&C[(size_t)row * EE + col] =
                make_float2(acc[mt][nt][0], acc[mt][nt][1]);
            *(float2*)&C[(size_t)(row + 8) * EE + col] =
                make_float2(acc[mt][nt][2], acc[mt][nt][3]);
        }
    }
}

// ---------------------------------------------------------------------------
// Epilogue: RoPE + RMS-norm on q (16 heads) and k (4 heads); gated ve add
// on v (4 heads). One warp per (token, unit), unit in [0,24). (UNCHANGED)
// ---------------------------------------------------------------------------
__global__ void __launch_bounds__(128) rope_gate(
    const float* __restrict__ X, const float* __restrict__ VE,
    const float* __restrict__ Cos, const float* __restrict__ Sin,
    const float* __restrict__ Wgate)
{
    const int gw = blockIdx.x * 4 + (threadIdx.x >> 5);
    const int lane = threadIdx.x & 31;
    const int token = gw / 24;
    const int unit = gw - token * 24;
    const int s = token & (SS - 1);

    if (unit >= 20) {  // v gate
        const int kv = unit - 20;
        const float* xr = X + (size_t)token * EE;
        float g = 0.f;
        #pragma unroll
        for (int c = 0; c < GCH; c++) g = fmaf(xr[c], Wgate[kv * GCH + c], g);
        g = 3.f / (1.f + __expf(-g));
        float* vb = g_v + (size_t)token * KVDIM + kv * HDD;
        const float* veb = VE + (size_t)token * KVDIM + kv * HDD;
        vb[lane]      += g * veb[lane];
        vb[lane + 32] += g * veb[lane + 32];
        return;
    }

    float* base = (unit < NHH)
        ? g_q + (size_t)token * QDIM + unit * HDD
        : g_k + (size_t)token * KVDIM + (unit - NHH) * HDD;

    const float c  = Cos[s * 32 + lane];
    const float sn = Sin[s * 32 + lane];
    const float x1 = base[lane];
    const float x2 = base[lane + 32];
    const float o1 =  x1 * c + x2 * sn;
    const float o2 = -x1 * sn + x2 * c;
    float ssum = o1 * o1 + o2 * o2;
    #pragma unroll
    for (int off = 16; off; off >>= 1)
        ssum += __shfl_xor_sync(0xffffffffu, ssum, off);
    const float inv = rsqrtf(ssum * (1.f / 64.f) + 1.1920928955078125e-07f) * 1.2f;
    base[lane]      = o1 * inv;
    base[lane + 32] = o2 * inv;
}

// ---------------------------------------------------------------------------
// Flash attention, GQA-shared, CONSTANT-MAX softmax.
// q,k are RMS-normed * 1.2 -> |score| <= 9.6^2/8 = 11.52 < 12, so
// exp(s - 12) never overflows (<=1 each, l <= 2048): the online max, O
// rescale, and the serial m/l chain are unnecessary and removed.
// Blocks issued heavy-first (qp reversed) to reduce the causal tail.
// smem: Qs 128x72 | Ks 64x72 | Vs 64x72 = 73728 B (dynamic)
// ---------------------------------------------------------------------------
#define APAD 72
#define ATTN_SMEM_BYTES (256 * APAD * 4)
#define SMAX 12.0f

__global__ void __launch_bounds__(256) attn_kernel()
{
    extern __shared__ unsigned sm[];
    unsigned* Qs = sm;                  // reused as P after frag extraction
    unsigned* Ks = sm + 128 * APAD;
    unsigned* Vs = sm + 192 * APAD;

    const int qp  = gridDim.x - 1 - blockIdx.x;  // heavy blocks first
    const int hkv = blockIdx.y;         // kv head (4)
    const int b   = blockIdx.z;         // batch (2)
    const int q0  = qp * 32;
    const int tid = threadIdx.x;
    const int lane = tid & 31;
    const int wid = tid >> 5;           // 0..7
    const int gy = lane >> 2;
    const int gx = lane & 3;
    const int r0 = wid * 16 + gy;       // virtual row (head*32 + pos offset)
    const int h  = hkv * 4 + (wid >> 1);
    const int pos0 = q0 + ((wid & 1) * 16 + gy);
    const int pos1 = pos0 + 8;

    // Stage Q (scaled by 1/8), interleaved tf32
    for (int idx = tid; idx < 128 * 16; idx += 256) {
        const int r = idx >> 4, c4 = (idx & 15) * 4;
        const float4 v = *(const float4*)&g_q[(size_t)(b * SS + q0 + (r & 31)) * QDIM
                                              + (hkv * 4 + (r >> 5)) * HDD + c4];
        unsigned* q = &Qs[r * APAD + (c4 & ~7) + ((c4 >> 2) & 1)];
        q[0] = f2tf(v.x * 0.125f); q[2] = f2tf(v.y * 0.125f);
        q[4] = f2tf(v.z * 0.125f); q[6] = f2tf(v.w * 0.125f);
    }
    __syncthreads();

    // Extract Q fragments (reused across all kv tiles)
    unsigned qa[8][4];
    #pragma unroll
    for (int ks = 0; ks < 8; ks++) {
        const uint2 lo = *(const uint2*)&Qs[r0 * APAD + ks * 8 + 2 * gx];
        const uint2 hi = *(const uint2*)&Qs[(r0 + 8) * APAD + ks * 8 + 2 * gx];
        qa[ks][0] = lo.x; qa[ks][1] = hi.x; qa[ks][2] = lo.y; qa[ks][3] = hi.y;
    }

    float Oa[8][4];
    #pragma unroll
    for (int nt = 0; nt < 8; nt++)
        #pragma unroll
        for (int e = 0; e < 4; e++) Oa[nt][e] = 0.f;
    float l0 = 0.f, l1 = 0.f;

    const int ntiles = (q0 + 95) >> 6;
    const int c4s  = (tid & 15) * 4;
    const int rb   = tid >> 4;                         // 0..15
    const int soff = (c4s & ~7) + ((c4s >> 2) & 1);
    const int pg   = (gy & 3) * 2 + (gy >> 2);         // interleaved col of gy
    const int pc0  = ((2 * gx) & 3) * 2 + (((2 * gx) >> 2) & 1);
    const int pc1  = ((2 * gx + 1) & 3) * 2 + (((2 * gx + 1) >> 2) & 1);
    const float* kp = g_k + (size_t)(b * SS) * KVDIM + hkv * HDD + c4s;
    const float* vp = g_v + (size_t)(b * SS) * KVDIM + hkv * HDD + c4s;

    float4 rk[4], rv[4];
    #pragma unroll
    for (int c = 0; c < 4; c++) {
        const size_t ro = (size_t)(rb + 16 * c) * KVDIM;
        rk[c] = *(const float4*)(kp + ro);
        rv[c] = *(const float4*)(vp + ro);
    }

    for (int j = 0; j < ntiles; j++) {
        __syncthreads();   // prior tile's consumers (incl. P in Qs) done
        #pragma unroll
        for (int c = 0; c < 4; c++) {
            unsigned* kd = &Ks[(rb + 16 * c) * APAD + soff];
            kd[0] = f2tf(rk[c].x); kd[2] = f2tf(rk[c].y);
            kd[4] = f2tf(rk[c].z); kd[6] = f2tf(rk[c].w);
            unsigned* vd = &Vs[(rb + 16 * c) * APAD + soff];
            vd[0] = f2tf(rv[c].x); vd[2] = f2tf(rv[c].y);
            vd[4] = f2tf(rv[c].z); vd[6] = f2tf(rv[c].w);
        }
        __syncthreads();
        if (j + 1 < ntiles) {  // prefetch next tile (latency hidden by mmas)
            const size_t tb = (size_t)((j + 1) * 64) * KVDIM;
            #pragma unroll
            for (int c = 0; c < 4; c++) {
                const size_t ro = tb + (size_t)(rb + 16 * c) * KVDIM;
                rk[c] = *(const float4*)(kp + ro);
                rv[c] = *(const float4*)(vp + ro);
            }
        }

        // S = Q K^T
        float sf[8][4];
        #pragma unroll
        for (int nt = 0; nt < 8; nt++)
            #pragma unroll
            for (int e = 0; e < 4; e++) sf[nt][e] = 0.f;
        #pragma unroll
        for (int ks = 0; ks < 8; ks++) {
            #pragma unroll
            for (int nt = 0; nt < 8; nt++) {
                const uint2 kb = *(const uint2*)&Ks[(nt * 8 + gy) * APAD + ks * 8 + 2 * gx];
                mma8(sf[nt], qa[ks][0], qa[ks][1], qa[ks][2], qa[ks][3], kb.x, kb.y);
            }
        }

        // causal mask (last tile only); scale folded into Q
        if (j == ntiles - 1) {
            #pragma unroll
            for (int nt = 0; nt < 8; nt++) {
                const int c = j * 64 + nt * 8 + 2 * gx;
                if (c     > pos0) sf[nt][0] = -1e30f;
                if (c + 1 > pos0) sf[nt][1] = -1e30f;
                if (c     > pos1) sf[nt][2] = -1e30f;
                if (c + 1 > pos1) sf[nt][3] = -1e30f;
            }
        }

        // fixed-max softmax: p = exp(s - SMAX), accumulate row sums
        float ps0 = 0.f, ps1 = 0.f;
        #pragma unroll
        for (int nt = 0; nt < 8; nt++) {
            sf[nt][0] = __expf(sf[nt][0] - SMAX);
            sf[nt][1] = __expf(sf[nt][1] - SMAX);
            sf[nt][2] = __expf(sf[nt][2] - SMAX);
            sf[nt][3] = __expf(sf[nt][3] - SMAX);
            ps0 += sf[nt][0] + sf[nt][1];
            ps1 += sf[nt][2] + sf[nt][3];
        }
        l0 += ps0;
        l1 += ps1;

        // store P (interleaved) into Q buffer: warp-private 16-row band
        #pragma unroll
        for (int nt = 0; nt < 8; nt++) {
            const int a = r0 * APAD + nt * 8;
            Qs[a + pc0] = f2tf(sf[nt][0]);
            Qs[a + pc1] = f2tf(sf[nt][1]);
            Qs[a + 8 * APAD + pc0] = f2tf(sf[nt][2]);
            Qs[a + 8 * APAD + pc1] = f2tf(sf[nt][3]);
        }
        __syncwarp();

        // O += P V  (no rescale needed: max is constant)
        #pragma unroll
        for (int ks = 0; ks < 8; ks++) {
            const uint2 plo = *(const uint2*)&Qs[r0 * APAD + ks * 8 + 2 * gx];
            const uint2 phi = *(const uint2*)&Qs[(r0 + 8) * APAD + ks * 8 + 2 * gx];
            #pragma unroll
            for (int nt = 0; nt < 8; nt++) {
                const int vb = (ks * 8 + gx) * APAD + nt * 8 + pg;
                mma8(Oa[nt], plo.x, phi.x, plo.y, phi.y, Vs[vb], Vs[vb + 4 * APAD]);
            }
        }
    }

    // row-sum reduction across the 4-lane groups (was fused with max before)
    l0 += __shfl_xor_sync(0xffffffffu, l0, 1);
    l0 += __shfl_xor_sync(0xffffffffu, l0, 2);
    l1 += __shfl_xor_sync(0xffffffffu, l1, 1);
    l1 += __shfl_xor_sync(0xffffffffu, l1, 2);

    // epilogue: normalize and store
    const float inv0 = 1.f / l0;
    const float inv1 = 1.f / l1;
    const size_t row0 = (size_t)(b * SS + pos0) * QDIM + h * HDD;
    const size_t row1 = (size_t)(b * SS + pos1) * QDIM + h * HDD;
    #pragma unroll
    for (int nt = 0; nt < 8; nt++) {
        const int col = nt * 8 + 2 * gx;
        *(float2*)&g_y[row0 + col] = make_float2(Oa[nt][0] * inv0, Oa[nt][1] * inv0);
        *(float2*)&g_y[row1 + col] = make_float2(Oa[nt][2] * inv1, Oa[nt][3] * inv1);
    }
}

// ---------------------------------------------------------------------------
// Launch: qkv GEMM -> rope/rms/gate -> flash attention -> proj GEMM
// Inputs: 0 x, 1 ve, 2 cos, 3 sin, 4 attn_mask(unused), 5 Wq, 6 Wk, 7 Wv,
//         8 Wproj, 9 Wgate. Output: float32 (B,S,E).
// ---------------------------------------------------------------------------
extern "C" void kernel_launch(void* const* d_in, const int* in_sizes, int n_in,
                              void* d_out, int out_size)
{
    const float* x     = (const float*)d_in[0];
    const float* ve    = (const float*)d_in[1];
    const float* cosb  = (const float*)d_in[2];
    const float* sinb  = (const float*)d_in[3];
    const float* Wq    = (const float*)d_in[5];
    const float* Wk    = (const float*)d_in[6];
    const float* Wv    = (const float*)d_in[7];
    const float* Wproj = (const float*)d_in[8];
    const float* Wgate = (const float*)d_in[9];
    float* out = (float*)d_out;

    (void)in_sizes; (void)n_in; (void)out_size;

    cudaFuncSetAttribute(attn_kernel,
                         cudaFuncAttributeMaxDynamicSharedMemorySize,
                         ATTN_SMEM_BYTES);

    // 1) QKV projection: grid (1536/128, 4096/128)
    gemm_qkv<<<dim3(12, 32), 256>>>(x, Wq, Wk, Wv);

    // 2) RoPE + RMS + gated-ve
    rope_gate<<<(MM * 24) / 4, 128>>>(x, ve, cosb, sinb, Wgate);

    // 3) Flash attention (GQA-shared, heavy-first): (pos-tiles, kv heads, batch)
    attn_kernel<<<dim3(SS / 32, NKVV, BB), 256, ATTN_SMEM_BYTES>>>();

    // 4) Output projection: grid (1024/128, 4096/128)
    gemm_proj<<<dim3(8, 32), 256>>>(Wproj, out);
}